// round 1
// baseline (speedup 1.0000x reference)
#include <cuda_runtime.h>
#include <math.h>

#define NN 10000
#define FF 128
#define PP 4
#define EE 160000
#define CC 512
#define HIDN 256
#define C4 (CC/4)

// ---------------- scratch (static device memory; no allocations) ----------------
__device__ float g_deg[NN];
__device__ float g_dinv[NN];
__device__ float g_normself[NN];
__device__ int   g_counts[NN];
__device__ int   g_rowptr[NN + 1];
__device__ int   g_cursor[NN];
__device__ int   g_csrsrc[EE];
__device__ float g_csrnorm[EE];
__device__ float g_probs[PP];

__device__ float g_Xp[NN * FF];
__device__ float g_T[NN * CC];
__device__ float g_BA[NN * CC];
__device__ float g_BB[NN * CC];
__device__ float g_H[NN * CC];
__device__ float g_Gz[NN * CC];
__device__ float g_Gr[NN * CC];
__device__ float g_Gh[NN * CC];
__device__ float g_Z[NN * CC];
__device__ float g_R[NN * CC];
__device__ float g_Ht[NN * CC];
__device__ float g_Hacc[NN * CC];
__device__ float g_hid1[NN * HIDN];

// ---------------- graph setup kernels ----------------
__global__ void init_node_arrays() {
    int i = blockIdx.x * blockDim.x + threadIdx.x;
    if (i < NN) {
        g_deg[i] = 0.0f;
        g_counts[i] = 0;
        g_cursor[i] = 0;
    }
}

__global__ void deg_edges_kernel(const int* __restrict__ ei, const float* __restrict__ ea) {
    int e = blockIdx.x * blockDim.x + threadIdx.x;
    if (e < EE) {
        int dst = ei[EE + e];
        atomicAdd(&g_deg[dst], ea[e]);
        atomicAdd(&g_counts[dst], 1);
    }
}

__global__ void deg_finalize_kernel() {
    int i = blockIdx.x * blockDim.x + threadIdx.x;
    if (i < NN) {
        float d = g_deg[i] + 1.0f;  // self loop weight 1
        float di = (d > 0.0f) ? rsqrtf(d) : 0.0f;
        g_dinv[i] = di;
        g_normself[i] = di * di;
    }
}

// single-block exclusive scan over g_counts -> g_rowptr
__global__ void scan_kernel() {
    __shared__ int part[1024];
    const int per = 10;  // 1024*10 >= 10000
    int t = threadIdx.x;
    int base = t * per;
    int loc[per];
    int s = 0;
#pragma unroll
    for (int i = 0; i < per; i++) {
        int idx = base + i;
        int v = (idx < NN) ? g_counts[idx] : 0;
        loc[i] = s;
        s += v;
    }
    part[t] = s;
    __syncthreads();
    for (int off = 1; off < 1024; off <<= 1) {
        int v = (t >= off) ? part[t - off] : 0;
        __syncthreads();
        part[t] += v;
        __syncthreads();
    }
    int offb = (t == 0) ? 0 : part[t - 1];
#pragma unroll
    for (int i = 0; i < per; i++) {
        int idx = base + i;
        if (idx < NN) g_rowptr[idx] = offb + loc[i];
    }
    if (t == 1023) g_rowptr[NN] = part[1023];
}

__global__ void scatter_kernel(const int* __restrict__ ei, const float* __restrict__ ea) {
    int e = blockIdx.x * blockDim.x + threadIdx.x;
    if (e < EE) {
        int src = ei[e];
        int dst = ei[EE + e];
        float nv = g_dinv[src] * ea[e] * g_dinv[dst];
        int pos = atomicAdd(&g_cursor[dst], 1);
        int slot = g_rowptr[dst] + pos;
        g_csrsrc[slot] = src;
        g_csrnorm[slot] = nv;
    }
}

__global__ void softmax4_kernel(const float* __restrict__ attn) {
    if (threadIdx.x == 0 && blockIdx.x == 0) {
        float m = attn[0];
        for (int p = 1; p < PP; p++) m = fmaxf(m, attn[p]);
        float s = 0.0f, e[PP];
        for (int p = 0; p < PP; p++) { e[p] = expf(attn[p] - m); s += e[p]; }
        for (int p = 0; p < PP; p++) g_probs[p] = e[p] / s;
    }
}

// ---------------- GEMM: C[M,Nc] = A[M,K] @ B[K,Nc]  (optionally +=) ----------------
#define BM 128
#define BN 64
#define BK 16

template <bool ACC>
__global__ void __launch_bounds__(256) gemm_kernel(
    const float* __restrict__ A, const float* __restrict__ B, float* __restrict__ Cm,
    int M, int Nc, int K) {
    __shared__ float As[BK][BM + 4];
    __shared__ float Bs[BK][BN + 4];
    int tid = threadIdx.x;
    int tx = tid & 15;       // 0..15 -> 4 cols each
    int ty = tid >> 4;       // 0..15 -> 8 rows each
    int m0 = blockIdx.y * BM;
    int n0 = blockIdx.x * BN;

    float acc[8][4];
#pragma unroll
    for (int i = 0; i < 8; i++)
#pragma unroll
        for (int j = 0; j < 4; j++) acc[i][j] = 0.0f;

    for (int k0 = 0; k0 < K; k0 += BK) {
#pragma unroll
        for (int i = 0; i < 8; i++) {
            int lin = tid + i * 256;
            int mm = lin >> 4;
            int kk = lin & 15;
            int m = m0 + mm;
            As[kk][mm] = (m < M) ? A[(size_t)m * K + k0 + kk] : 0.0f;
        }
#pragma unroll
        for (int i = 0; i < 4; i++) {
            int lin = tid + i * 256;
            int nn = lin & 63;
            int kk = lin >> 6;
            Bs[kk][nn] = B[(size_t)(k0 + kk) * Nc + n0 + nn];
        }
        __syncthreads();
#pragma unroll
        for (int k = 0; k < BK; k++) {
            float bv[4];
#pragma unroll
            for (int j = 0; j < 4; j++) bv[j] = Bs[k][tx * 4 + j];
#pragma unroll
            for (int i = 0; i < 8; i++) {
                float av = As[k][ty * 8 + i];
#pragma unroll
                for (int j = 0; j < 4; j++) acc[i][j] = fmaf(av, bv[j], acc[i][j]);
            }
        }
        __syncthreads();
    }

#pragma unroll
    for (int i = 0; i < 8; i++) {
        int m = m0 + ty * 8 + i;
        if (m < M) {
            float* cp = &Cm[(size_t)m * Nc + n0 + tx * 4];
            if (ACC) {
                float4 old = *(float4*)cp;
                old.x += acc[i][0]; old.y += acc[i][1];
                old.z += acc[i][2]; old.w += acc[i][3];
                *(float4*)cp = old;
            } else {
                *(float4*)cp = make_float4(acc[i][0], acc[i][1], acc[i][2], acc[i][3]);
            }
        }
    }
}

// ---------------- GCN propagation: out[i] = bias + selfnorm[i]*T[i] + sum_edges norm*T[src] ----------------
__global__ void __launch_bounds__(128) prop_kernel(
    const float* __restrict__ T, const float* __restrict__ bias, float* __restrict__ out) {
    int i = blockIdx.x;
    int t = threadIdx.x;
    const float4* T4 = (const float4*)T;
    float4 b = ((const float4*)bias)[t];
    float sn = g_normself[i];
    float4 v = T4[(size_t)i * C4 + t];
    float4 acc = make_float4(b.x + sn * v.x, b.y + sn * v.y, b.z + sn * v.z, b.w + sn * v.w);
    int beg = g_rowptr[i];
    int end = g_rowptr[i + 1];
    for (int e = beg; e < end; e++) {
        int s = g_csrsrc[e];
        float w = g_csrnorm[e];
        float4 u = T4[(size_t)s * C4 + t];
        acc.x = fmaf(w, u.x, acc.x);
        acc.y = fmaf(w, u.y, acc.y);
        acc.z = fmaf(w, u.z, acc.z);
        acc.w = fmaf(w, u.w, acc.w);
    }
    ((float4*)out)[(size_t)i * C4 + t] = acc;
}

// ---------------- elementwise kernels ----------------
__global__ void extract_kernel(const float* __restrict__ x, int p) {
    int idx = blockIdx.x * blockDim.x + threadIdx.x;
    if (idx < NN * FF) g_Xp[idx] = x[(size_t)idx * PP + p];
}

__global__ void zero_f_kernel(float* __restrict__ a, int n) {
    int idx = blockIdx.x * blockDim.x + threadIdx.x;
    if (idx < n) a[idx] = 0.0f;
}

__global__ void sigmoid_bias_kernel(float* __restrict__ buf, const float* __restrict__ bias) {
    int idx = blockIdx.x * blockDim.x + threadIdx.x;
    if (idx < NN * CC) {
        int c = idx & (CC - 1);
        float v = buf[idx] + bias[c];
        buf[idx] = 1.0f / (1.0f + expf(-v));
    }
}

__global__ void tanh_bias_kernel(float* __restrict__ buf, const float* __restrict__ bias) {
    int idx = blockIdx.x * blockDim.x + threadIdx.x;
    if (idx < NN * CC) {
        int c = idx & (CC - 1);
        buf[idx] = tanhf(buf[idx] + bias[c]);
    }
}

__global__ void hadamard_kernel(float* __restrict__ r, const float* __restrict__ h) {
    int idx = blockIdx.x * blockDim.x + threadIdx.x;
    if (idx < NN * CC) r[idx] *= h[idx];
}

__global__ void gru_acc_kernel(const float* __restrict__ Z, const float* __restrict__ H,
                               const float* __restrict__ Ht, float* __restrict__ Hacc, int p) {
    int idx = blockIdx.x * blockDim.x + threadIdx.x;
    if (idx < NN * CC) {
        float pr = g_probs[p];
        float z = Z[idx];
        float hn = z * H[idx] + (1.0f - z) * Ht[idx];
        Hacc[idx] += pr * hn;
    }
}

__global__ void relu_copy_kernel(const float* __restrict__ src, float* __restrict__ dst) {
    int idx = blockIdx.x * blockDim.x + threadIdx.x;
    if (idx < NN * CC) dst[idx] = fmaxf(src[idx], 0.0f);
}

__global__ void relu_bias_kernel(float* __restrict__ buf, const float* __restrict__ bias) {
    int idx = blockIdx.x * blockDim.x + threadIdx.x;
    if (idx < NN * HIDN) {
        int c = idx % HIDN;
        buf[idx] = fmaxf(buf[idx] + bias[c], 0.0f);
    }
}

// final 256->1 projection: one warp per node, result into d_out[0..NN)
__global__ void lin2_kernel(const float* __restrict__ hid, const float* __restrict__ w,
                            const float* __restrict__ b, float* __restrict__ out) {
    int n = blockIdx.x * 8 + (threadIdx.x >> 5);
    int lane = threadIdx.x & 31;
    float s = 0.0f;
    for (int k = lane; k < HIDN; k += 32) s = fmaf(hid[(size_t)n * HIDN + k], w[k], s);
#pragma unroll
    for (int off = 16; off; off >>= 1) s += __shfl_down_sync(0xffffffffu, s, off);
    if (lane == 0) out[n] = s + b[0];
}

__global__ void copy_hidden_kernel(const float* __restrict__ Hacc, float* __restrict__ out) {
    int idx = blockIdx.x * blockDim.x + threadIdx.x;
    if (idx < NN * C4) {
        ((float4*)(out + NN))[idx] = ((const float4*)Hacc)[idx];
    }
}

// ---------------- host orchestration ----------------
static inline void launch_gemm(const float* A, const float* B, float* C,
                               int M, int Nc, int K, bool acc) {
    dim3 grid(Nc / BN, (M + BM - 1) / BM);
    if (acc) gemm_kernel<true><<<grid, 256>>>(A, B, C, M, Nc, K);
    else     gemm_kernel<false><<<grid, 256>>>(A, B, C, M, Nc, K);
}

extern "C" void kernel_launch(void* const* d_in, const int* in_sizes, int n_in,
                              void* d_out, int out_size) {
    const float* x     = (const float*)d_in[0];
    const int*   ei    = (const int*)d_in[1];
    const float* ea    = (const float*)d_in[2];
    const float* W1    = (const float*)d_in[3];
    const float* b1    = (const float*)d_in[4];
    const float* W2    = (const float*)d_in[5];
    const float* b2    = (const float*)d_in[6];
    const float* W3    = (const float*)d_in[7];
    const float* b3    = (const float*)d_in[8];
    const float* W4    = (const float*)d_in[9];
    const float* b4    = (const float*)d_in[10];
    const float* W5    = (const float*)d_in[11];
    const float* b5    = (const float*)d_in[12];
    const float* Wz    = (const float*)d_in[13];
    const float* bz    = (const float*)d_in[14];
    const float* Lz_w  = (const float*)d_in[15];
    const float* Lz_b  = (const float*)d_in[16];
    const float* Wr    = (const float*)d_in[17];
    const float* br    = (const float*)d_in[18];
    const float* Lr_w  = (const float*)d_in[19];
    const float* Lr_b  = (const float*)d_in[20];
    const float* Wh    = (const float*)d_in[21];
    const float* bh    = (const float*)d_in[22];
    const float* Lh_w  = (const float*)d_in[23];
    const float* Lh_b  = (const float*)d_in[24];
    const float* attn  = (const float*)d_in[25];
    const float* lin1w = (const float*)d_in[26];
    const float* lin1b = (const float*)d_in[27];
    const float* lin2w = (const float*)d_in[28];
    const float* lin2b = (const float*)d_in[29];
    float* out = (float*)d_out;

    float *pXp, *pT, *pBA, *pBB, *pH, *pGz, *pGr, *pGh, *pZ, *pR, *pHt, *pHacc, *phid1;
    cudaGetSymbolAddress((void**)&pXp, g_Xp);
    cudaGetSymbolAddress((void**)&pT, g_T);
    cudaGetSymbolAddress((void**)&pBA, g_BA);
    cudaGetSymbolAddress((void**)&pBB, g_BB);
    cudaGetSymbolAddress((void**)&pH, g_H);
    cudaGetSymbolAddress((void**)&pGz, g_Gz);
    cudaGetSymbolAddress((void**)&pGr, g_Gr);
    cudaGetSymbolAddress((void**)&pGh, g_Gh);
    cudaGetSymbolAddress((void**)&pZ, g_Z);
    cudaGetSymbolAddress((void**)&pR, g_R);
    cudaGetSymbolAddress((void**)&pHt, g_Ht);
    cudaGetSymbolAddress((void**)&pHacc, g_Hacc);
    cudaGetSymbolAddress((void**)&phid1, g_hid1);

    const int gE  = (EE + 255) / 256;
    const int gN  = (NN + 255) / 256;
    const int gNC = (NN * CC + 255) / 256;
    const int gNF = (NN * FF + 255) / 256;

    // graph normalization + CSR build (deterministic row-wise sums thereafter)
    init_node_arrays<<<gN, 256>>>();
    deg_edges_kernel<<<gE, 256>>>(ei, ea);
    deg_finalize_kernel<<<gN, 256>>>();
    scan_kernel<<<1, 1024>>>();
    scatter_kernel<<<gE, 256>>>(ei, ea);
    softmax4_kernel<<<1, 32>>>(attn);
    zero_f_kernel<<<gNC, 256>>>(pHacc, NN * CC);

    for (int p = 0; p < PP; p++) {
        extract_kernel<<<gNF, 256>>>(x, p);

        // 5-layer GCN chain
        launch_gemm(pXp, W1, pT, NN, CC, FF, false);
        prop_kernel<<<NN, 128>>>(pT, b1, pBA);
        launch_gemm(pBA, W2, pT, NN, CC, CC, false);
        prop_kernel<<<NN, 128>>>(pT, b2, pBB);
        launch_gemm(pBB, W3, pT, NN, CC, CC, false);
        prop_kernel<<<NN, 128>>>(pT, b3, pBA);
        launch_gemm(pBA, W4, pT, NN, CC, CC, false);
        prop_kernel<<<NN, 128>>>(pT, b4, pBB);
        launch_gemm(pBB, W5, pT, NN, CC, CC, false);
        prop_kernel<<<NN, 128>>>(pT, b5, pH);

        // gate inputs
        launch_gemm(pXp, Wz, pT, NN, CC, FF, false);
        prop_kernel<<<NN, 128>>>(pT, bz, pGz);
        launch_gemm(pXp, Wr, pT, NN, CC, FF, false);
        prop_kernel<<<NN, 128>>>(pT, br, pGr);
        launch_gemm(pXp, Wh, pT, NN, CC, FF, false);
        prop_kernel<<<NN, 128>>>(pT, bh, pGh);

        // Z = sigmoid([Gz, H] @ Lz_w + Lz_b)  (split K=1024 into two K=512 GEMMs)
        launch_gemm(pGz, Lz_w, pZ, NN, CC, CC, false);
        launch_gemm(pH, Lz_w + (size_t)CC * CC, pZ, NN, CC, CC, true);
        sigmoid_bias_kernel<<<gNC, 256>>>(pZ, Lz_b);

        // R = sigmoid([Gr, H] @ Lr_w + Lr_b)
        launch_gemm(pGr, Lr_w, pR, NN, CC, CC, false);
        launch_gemm(pH, Lr_w + (size_t)CC * CC, pR, NN, CC, CC, true);
        sigmoid_bias_kernel<<<gNC, 256>>>(pR, Lr_b);

        // R <- H * R
        hadamard_kernel<<<gNC, 256>>>(pR, pH);

        // Ht = tanh([Gh, H*R] @ Lh_w + Lh_b)
        launch_gemm(pGh, Lh_w, pHt, NN, CC, CC, false);
        launch_gemm(pR, Lh_w + (size_t)CC * CC, pHt, NN, CC, CC, true);
        tanh_bias_kernel<<<gNC, 256>>>(pHt, Lh_b);

        // Hacc += probs[p] * (Z*H + (1-Z)*Ht)
        gru_acc_kernel<<<gNC, 256>>>(pZ, pH, pHt, pHacc, p);
    }

    // head: out_hidden = Hacc ; h = relu(Hacc) @ lin1 -> relu -> @ lin2
    relu_copy_kernel<<<gNC, 256>>>(pHacc, pBA);
    launch_gemm(pBA, lin1w, phid1, NN, HIDN, CC, false);
    relu_bias_kernel<<<(NN * HIDN + 255) / 256, 256>>>(phid1, lin1b);
    lin2_kernel<<<(NN + 7) / 8, 256>>>(phid1, lin2w, lin2b, out);
    copy_hidden_kernel<<<(NN * C4 + 255) / 256, 256>>>(pHacc, out);
}

// round 3
// speedup vs baseline: 1.1095x; 1.1095x over previous
#include <cuda_runtime.h>
#include <cuda_bf16.h>
#include <stdint.h>
#include <math.h>

#define NN 10000
#define FF 128
#define PP 4
#define EE 160000
#define CC 512
#define HIDN 256
#define C4 (CC/4)

// ---------------- scratch (static device memory; no allocations) ----------------
__device__ float g_deg[NN];
__device__ float g_dinv[NN];
__device__ float g_normself[NN];
__device__ int   g_counts[NN];
__device__ int   g_rowptr[NN + 1];
__device__ int   g_cursor[NN];
__device__ int   g_csrsrc[EE];
__device__ float g_csrnorm[EE];
__device__ float g_probs[PP];

__device__ float g_Xp[NN * FF];
__device__ float g_T[NN * CC];
__device__ float g_BA[NN * CC];
__device__ float g_BB[NN * CC];
__device__ float g_H[NN * CC];
__device__ float g_Gz[NN * CC];
__device__ float g_Gr[NN * CC];
__device__ float g_Gh[NN * CC];
__device__ float g_Z[NN * CC];
__device__ float g_R[NN * CC];
__device__ float g_Ht[NN * CC];
__device__ float g_Hacc[NN * CC];
__device__ float g_hid1[NN * HIDN];

// ---------------- graph setup kernels ----------------
__global__ void init_node_arrays() {
    int i = blockIdx.x * blockDim.x + threadIdx.x;
    if (i < NN) {
        g_deg[i] = 0.0f;
        g_counts[i] = 0;
        g_cursor[i] = 0;
    }
}

__global__ void deg_edges_kernel(const int* __restrict__ ei, const float* __restrict__ ea) {
    int e = blockIdx.x * blockDim.x + threadIdx.x;
    if (e < EE) {
        int dst = ei[EE + e];
        atomicAdd(&g_deg[dst], ea[e]);
        atomicAdd(&g_counts[dst], 1);
    }
}

__global__ void deg_finalize_kernel() {
    int i = blockIdx.x * blockDim.x + threadIdx.x;
    if (i < NN) {
        float d = g_deg[i] + 1.0f;  // self loop weight 1
        float di = (d > 0.0f) ? rsqrtf(d) : 0.0f;
        g_dinv[i] = di;
        g_normself[i] = di * di;
    }
}

// single-block exclusive scan over g_counts -> g_rowptr
__global__ void scan_kernel() {
    __shared__ int part[1024];
    const int per = 10;  // 1024*10 >= 10000
    int t = threadIdx.x;
    int base = t * per;
    int loc[per];
    int s = 0;
#pragma unroll
    for (int i = 0; i < per; i++) {
        int idx = base + i;
        int v = (idx < NN) ? g_counts[idx] : 0;
        loc[i] = s;
        s += v;
    }
    part[t] = s;
    __syncthreads();
    for (int off = 1; off < 1024; off <<= 1) {
        int v = (t >= off) ? part[t - off] : 0;
        __syncthreads();
        part[t] += v;
        __syncthreads();
    }
    int offb = (t == 0) ? 0 : part[t - 1];
#pragma unroll
    for (int i = 0; i < per; i++) {
        int idx = base + i;
        if (idx < NN) g_rowptr[idx] = offb + loc[i];
    }
    if (t == 1023) g_rowptr[NN] = part[1023];
}

__global__ void scatter_kernel(const int* __restrict__ ei, const float* __restrict__ ea) {
    int e = blockIdx.x * blockDim.x + threadIdx.x;
    if (e < EE) {
        int src = ei[e];
        int dst = ei[EE + e];
        float nv = g_dinv[src] * ea[e] * g_dinv[dst];
        int pos = atomicAdd(&g_cursor[dst], 1);
        int slot = g_rowptr[dst] + pos;
        g_csrsrc[slot] = src;
        g_csrnorm[slot] = nv;
    }
}

__global__ void softmax4_kernel(const float* __restrict__ attn) {
    if (threadIdx.x == 0 && blockIdx.x == 0) {
        float m = attn[0];
        for (int p = 1; p < PP; p++) m = fmaxf(m, attn[p]);
        float s = 0.0f, e[PP];
        for (int p = 0; p < PP; p++) { e[p] = expf(attn[p] - m); s += e[p]; }
        for (int p = 0; p < PP; p++) g_probs[p] = e[p] / s;
    }
}

// ---------------- bf16x3 tensor-core GEMM ----------------
// C[M,Nc] = A[M,K] @ B[K,Nc]   (A,B,C fp32; internally split to bf16 hi/lo)
// Block tile 128x64, BK=16, 8 warps (4M x 2N), warp tile 32x32.
#define BM 128
#define BN 64
#define BKC 16
#define ASTR (BKC + 8)   /* 24 bf16 units */
#define BSTR (BKC + 8)

__device__ __forceinline__ uint32_t pack_bf2(__nv_bfloat16 lo, __nv_bfloat16 hi) {
    __nv_bfloat162 t(lo, hi);
    return *(uint32_t*)&t;
}

__device__ __forceinline__ void split_bf(float x, __nv_bfloat16& h, __nv_bfloat16& l) {
    h = __float2bfloat16(x);
    l = __float2bfloat16(x - __bfloat162float(h));
}

__device__ __forceinline__ void mma16816(float* c, const uint32_t* a, const uint32_t* b) {
    asm volatile(
        "mma.sync.aligned.m16n8k16.row.col.f32.bf16.bf16.f32 "
        "{%0,%1,%2,%3}, {%4,%5,%6,%7}, {%8,%9}, {%0,%1,%2,%3};"
        : "+f"(c[0]), "+f"(c[1]), "+f"(c[2]), "+f"(c[3])
        : "r"(a[0]), "r"(a[1]), "r"(a[2]), "r"(a[3]), "r"(b[0]), "r"(b[1]));
}

template <bool ACC>
__global__ void __launch_bounds__(256) mma_gemm_kernel(
    const float* __restrict__ A, const float* __restrict__ B, float* __restrict__ Cm,
    int M, int Nc, int K) {
    __shared__ __align__(16) __nv_bfloat16 As[2][2][BM * ASTR];
    __shared__ __align__(16) __nv_bfloat16 Bs[2][2][BN * BSTR];

    int tid = threadIdx.x;
    int m0 = blockIdx.y * BM;
    int n0 = blockIdx.x * BN;
    int warp = tid >> 5, lane = tid & 31;
    int wm = warp >> 1;      // 0..3
    int wn = warp & 1;       // 0..1
    int g = lane >> 2, tg = lane & 3;

    float c[2][4][4];
#pragma unroll
    for (int mt = 0; mt < 2; mt++)
#pragma unroll
        for (int nt = 0; nt < 4; nt++)
#pragma unroll
            for (int i = 0; i < 4; i++) c[mt][nt][i] = 0.0f;

    // prefetch registers
    float4 areg[2];
    float4 breg;

    // A tile: 128 rows x 16 cols = 512 float4; 2 per thread
    int a_row0 = (tid) >> 2;
    int a_c4_0 = (tid) & 3;
    int a_row1 = (tid + 256) >> 2;
    int a_c4_1 = (tid + 256) & 3;
    // B tile: 16 rows x 64 cols = 256 float4; 1 per thread
    int b_k = tid >> 4;
    int b_nf = tid & 15;

    auto load_glb = [&](int k0) {
        int m = m0 + a_row0;
        areg[0] = (m < M) ? *(const float4*)&A[(size_t)m * K + k0 + a_c4_0 * 4]
                          : make_float4(0.f, 0.f, 0.f, 0.f);
        m = m0 + a_row1;
        areg[1] = (m < M) ? *(const float4*)&A[(size_t)m * K + k0 + a_c4_1 * 4]
                          : make_float4(0.f, 0.f, 0.f, 0.f);
        breg = *(const float4*)&B[(size_t)(k0 + b_k) * Nc + n0 + b_nf * 4];
    };

    auto store_smem = [&](int buf) {
#pragma unroll
        for (int i = 0; i < 2; i++) {
            int row = i == 0 ? a_row0 : a_row1;
            int c4 = i == 0 ? a_c4_0 : a_c4_1;
            float4 v = areg[i];
            __nv_bfloat16 h0, h1, h2, h3, l0, l1, l2, l3;
            split_bf(v.x, h0, l0); split_bf(v.y, h1, l1);
            split_bf(v.z, h2, l2); split_bf(v.w, h3, l3);
            int off = row * ASTR + c4 * 4;
            *(uint2*)&As[buf][0][off] = make_uint2(pack_bf2(h0, h1), pack_bf2(h2, h3));
            *(uint2*)&As[buf][1][off] = make_uint2(pack_bf2(l0, l1), pack_bf2(l2, l3));
        }
        {
            float4 v = breg;
            float vv[4] = {v.x, v.y, v.z, v.w};
#pragma unroll
            for (int j = 0; j < 4; j++) {
                int n = b_nf * 4 + j;
                __nv_bfloat16 h, l;
                split_bf(vv[j], h, l);
                Bs[buf][0][n * BSTR + b_k] = h;
                Bs[buf][1][n * BSTR + b_k] = l;
            }
        }
    };

    auto compute = [&](int buf) {
        uint32_t af[2][2][4];
#pragma unroll
        for (int mt = 0; mt < 2; mt++) {
            int rb = wm * 32 + mt * 16;
#pragma unroll
            for (int h = 0; h < 2; h++) {
                const __nv_bfloat16* base = As[buf][h];
                af[mt][h][0] = *(const uint32_t*)&base[(rb + g) * ASTR + tg * 2];
                af[mt][h][1] = *(const uint32_t*)&base[(rb + g + 8) * ASTR + tg * 2];
                af[mt][h][2] = *(const uint32_t*)&base[(rb + g) * ASTR + tg * 2 + 8];
                af[mt][h][3] = *(const uint32_t*)&base[(rb + g + 8) * ASTR + tg * 2 + 8];
            }
        }
        uint32_t bfr[4][2][2];
#pragma unroll
        for (int nt = 0; nt < 4; nt++) {
            int nb = wn * 32 + nt * 8 + g;
#pragma unroll
            for (int h = 0; h < 2; h++) {
                const __nv_bfloat16* base = Bs[buf][h];
                bfr[nt][h][0] = *(const uint32_t*)&base[nb * BSTR + tg * 2];
                bfr[nt][h][1] = *(const uint32_t*)&base[nb * BSTR + tg * 2 + 8];
            }
        }
#pragma unroll
        for (int mt = 0; mt < 2; mt++)
#pragma unroll
            for (int nt = 0; nt < 4; nt++) {
                mma16816(c[mt][nt], af[mt][0], bfr[nt][0]);  // hi*hi
                mma16816(c[mt][nt], af[mt][1], bfr[nt][0]);  // lo*hi
                mma16816(c[mt][nt], af[mt][0], bfr[nt][1]);  // hi*lo
            }
    };

    int nchunks = K / BKC;
    load_glb(0);
    store_smem(0);
    __syncthreads();
    for (int ch = 0; ch < nchunks; ch++) {
        int buf = ch & 1;
        if (ch + 1 < nchunks) load_glb((ch + 1) * BKC);
        compute(buf);
        if (ch + 1 < nchunks) store_smem(buf ^ 1);
        __syncthreads();
    }

    // epilogue
#pragma unroll
    for (int mt = 0; mt < 2; mt++) {
#pragma unroll
        for (int nt = 0; nt < 4; nt++) {
            int row0 = m0 + wm * 32 + mt * 16 + g;
            int col = n0 + wn * 32 + nt * 8 + tg * 2;
            if (row0 < M) {
                float* cp = &Cm[(size_t)row0 * Nc + col];
                if (ACC) {
                    float2 old = *(float2*)cp;
                    old.x += c[mt][nt][0]; old.y += c[mt][nt][1];
                    *(float2*)cp = old;
                } else {
                    *(float2*)cp = make_float2(c[mt][nt][0], c[mt][nt][1]);
                }
            }
            int row1 = row0 + 8;
            if (row1 < M) {
                float* cp = &Cm[(size_t)row1 * Nc + col];
                if (ACC) {
                    float2 old = *(float2*)cp;
                    old.x += c[mt][nt][2]; old.y += c[mt][nt][3];
                    *(float2*)cp = old;
                } else {
                    *(float2*)cp = make_float2(c[mt][nt][2], c[mt][nt][3]);
                }
            }
        }
    }
}

// ---------------- GCN propagation: out[i] = bias + selfnorm[i]*T[i] + sum_edges norm*T[src] ----------------
__global__ void __launch_bounds__(128) prop_kernel(
    const float* __restrict__ T, const float* __restrict__ bias, float* __restrict__ out) {
    int i = blockIdx.x;
    int t = threadIdx.x;
    const float4* T4 = (const float4*)T;
    float4 b = ((const float4*)bias)[t];
    float sn = g_normself[i];
    float4 v = T4[(size_t)i * C4 + t];
    float4 acc = make_float4(b.x + sn * v.x, b.y + sn * v.y, b.z + sn * v.z, b.w + sn * v.w);
    int beg = g_rowptr[i];
    int end = g_rowptr[i + 1];
    for (int e = beg; e < end; e++) {
        int s = g_csrsrc[e];
        float w = g_csrnorm[e];
        float4 u = T4[(size_t)s * C4 + t];
        acc.x = fmaf(w, u.x, acc.x);
        acc.y = fmaf(w, u.y, acc.y);
        acc.z = fmaf(w, u.z, acc.z);
        acc.w = fmaf(w, u.w, acc.w);
    }
    ((float4*)out)[(size_t)i * C4 + t] = acc;
}

// ---------------- elementwise kernels ----------------
__global__ void extract_kernel(const float* __restrict__ x, int p) {
    int idx = blockIdx.x * blockDim.x + threadIdx.x;
    if (idx < NN * FF) g_Xp[idx] = x[(size_t)idx * PP + p];
}

__global__ void zero_f_kernel(float* __restrict__ a, int n) {
    int idx = blockIdx.x * blockDim.x + threadIdx.x;
    if (idx < n) a[idx] = 0.0f;
}

__global__ void sigmoid_bias_kernel(float* __restrict__ buf, const float* __restrict__ bias) {
    int idx = blockIdx.x * blockDim.x + threadIdx.x;
    if (idx < NN * CC) {
        int c = idx & (CC - 1);
        float v = buf[idx] + bias[c];
        buf[idx] = 1.0f / (1.0f + expf(-v));
    }
}

__global__ void tanh_bias_kernel(float* __restrict__ buf, const float* __restrict__ bias) {
    int idx = blockIdx.x * blockDim.x + threadIdx.x;
    if (idx < NN * CC) {
        int c = idx & (CC - 1);
        buf[idx] = tanhf(buf[idx] + bias[c]);
    }
}

__global__ void hadamard_kernel(float* __restrict__ r, const float* __restrict__ h) {
    int idx = blockIdx.x * blockDim.x + threadIdx.x;
    if (idx < NN * CC) r[idx] *= h[idx];
}

__global__ void gru_acc_kernel(const float* __restrict__ Z, const float* __restrict__ H,
                               const float* __restrict__ Ht, float* __restrict__ Hacc, int p) {
    int idx = blockIdx.x * blockDim.x + threadIdx.x;
    if (idx < NN * CC) {
        float pr = g_probs[p];
        float z = Z[idx];
        float hn = z * H[idx] + (1.0f - z) * Ht[idx];
        Hacc[idx] += pr * hn;
    }
}

__global__ void relu_copy_kernel(const float* __restrict__ src, float* __restrict__ dst) {
    int idx = blockIdx.x * blockDim.x + threadIdx.x;
    if (idx < NN * CC) dst[idx] = fmaxf(src[idx], 0.0f);
}

__global__ void relu_bias_kernel(float* __restrict__ buf, const float* __restrict__ bias) {
    int idx = blockIdx.x * blockDim.x + threadIdx.x;
    if (idx < NN * HIDN) {
        int c = idx % HIDN;
        buf[idx] = fmaxf(buf[idx] + bias[c], 0.0f);
    }
}

// final 256->1 projection: one warp per node, result into d_out[0..NN)
__global__ void lin2_kernel(const float* __restrict__ hid, const float* __restrict__ w,
                            const float* __restrict__ b, float* __restrict__ out) {
    int n = blockIdx.x * 8 + (threadIdx.x >> 5);
    int lane = threadIdx.x & 31;
    float s = 0.0f;
    for (int k = lane; k < HIDN; k += 32) s = fmaf(hid[(size_t)n * HIDN + k], w[k], s);
#pragma unroll
    for (int off = 16; off; off >>= 1) s += __shfl_down_sync(0xffffffffu, s, off);
    if (lane == 0) out[n] = s + b[0];
}

__global__ void copy_hidden_kernel(const float* __restrict__ Hacc, float* __restrict__ out) {
    int idx = blockIdx.x * blockDim.x + threadIdx.x;
    if (idx < NN * C4) {
        ((float4*)(out + NN))[idx] = ((const float4*)Hacc)[idx];
    }
}

// ---------------- host orchestration ----------------
static inline void launch_gemm(const float* A, const float* B, float* C,
                               int M, int Nc, int K, bool acc) {
    dim3 grid(Nc / BN, (M + BM - 1) / BM);
    if (acc) mma_gemm_kernel<true><<<grid, 256>>>(A, B, C, M, Nc, K);
    else     mma_gemm_kernel<false><<<grid, 256>>>(A, B, C, M, Nc, K);
}

extern "C" void kernel_launch(void* const* d_in, const int* in_sizes, int n_in,
                              void* d_out, int out_size) {
    const float* x     = (const float*)d_in[0];
    const int*   ei    = (const int*)d_in[1];
    const float* ea    = (const float*)d_in[2];
    const float* W1    = (const float*)d_in[3];
    const float* b1    = (const float*)d_in[4];
    const float* W2    = (const float*)d_in[5];
    const float* b2    = (const float*)d_in[6];
    const float* W3    = (const float*)d_in[7];
    const float* b3    = (const float*)d_in[8];
    const float* W4    = (const float*)d_in[9];
    const float* b4    = (const float*)d_in[10];
    const float* W5    = (const float*)d_in[11];
    const float* b5    = (const float*)d_in[12];
    const float* Wz    = (const float*)d_in[13];
    const float* bz    = (const float*)d_in[14];
    const float* Lz_w  = (const float*)d_in[15];
    const float* Lz_b  = (const float*)d_in[16];
    const float* Wr    = (const float*)d_in[17];
    const float* br    = (const float*)d_in[18];
    const float* Lr_w  = (const float*)d_in[19];
    const float* Lr_b  = (const float*)d_in[20];
    const float* Wh    = (const float*)d_in[21];
    const float* bh    = (const float*)d_in[22];
    const float* Lh_w  = (const float*)d_in[23];
    const float* Lh_b  = (const float*)d_in[24];
    const float* attn  = (const float*)d_in[25];
    const float* lin1w = (const float*)d_in[26];
    const float* lin1b = (const float*)d_in[27];
    const float* lin2w = (const float*)d_in[28];
    const float* lin2b = (const float*)d_in[29];
    float* out = (float*)d_out;

    float *pXp, *pT, *pBA, *pBB, *pH, *pGz, *pGr, *pGh, *pZ, *pR, *pHt, *pHacc, *phid1;
    cudaGetSymbolAddress((void**)&pXp, g_Xp);
    cudaGetSymbolAddress((void**)&pT, g_T);
    cudaGetSymbolAddress((void**)&pBA, g_BA);
    cudaGetSymbolAddress((void**)&pBB, g_BB);
    cudaGetSymbolAddress((void**)&pH, g_H);
    cudaGetSymbolAddress((void**)&pGz, g_Gz);
    cudaGetSymbolAddress((void**)&pGr, g_Gr);
    cudaGetSymbolAddress((void**)&pGh, g_Gh);
    cudaGetSymbolAddress((void**)&pZ, g_Z);
    cudaGetSymbolAddress((void**)&pR, g_R);
    cudaGetSymbolAddress((void**)&pHt, g_Ht);
    cudaGetSymbolAddress((void**)&pHacc, g_Hacc);
    cudaGetSymbolAddress((void**)&phid1, g_hid1);

    const int gE  = (EE + 255) / 256;
    const int gN  = (NN + 255) / 256;
    const int gNC = (NN * CC + 255) / 256;
    const int gNF = (NN * FF + 255) / 256;

    // graph normalization + CSR build (deterministic row-wise sums thereafter)
    init_node_arrays<<<gN, 256>>>();
    deg_edges_kernel<<<gE, 256>>>(ei, ea);
    deg_finalize_kernel<<<gN, 256>>>();
    scan_kernel<<<1, 1024>>>();
    scatter_kernel<<<gE, 256>>>(ei, ea);
    softmax4_kernel<<<1, 32>>>(attn);
    zero_f_kernel<<<gNC, 256>>>(pHacc, NN * CC);

    for (int p = 0; p < PP; p++) {
        extract_kernel<<<gNF, 256>>>(x, p);

        // 5-layer GCN chain
        launch_gemm(pXp, W1, pT, NN, CC, FF, false);
        prop_kernel<<<NN, 128>>>(pT, b1, pBA);
        launch_gemm(pBA, W2, pT, NN, CC, CC, false);
        prop_kernel<<<NN, 128>>>(pT, b2, pBB);
        launch_gemm(pBB, W3, pT, NN, CC, CC, false);
        prop_kernel<<<NN, 128>>>(pT, b3, pBA);
        launch_gemm(pBA, W4, pT, NN, CC, CC, false);
        prop_kernel<<<NN, 128>>>(pT, b4, pBB);
        launch_gemm(pBB, W5, pT, NN, CC, CC, false);
        prop_kernel<<<NN, 128>>>(pT, b5, pH);

        // gate inputs
        launch_gemm(pXp, Wz, pT, NN, CC, FF, false);
        prop_kernel<<<NN, 128>>>(pT, bz, pGz);
        launch_gemm(pXp, Wr, pT, NN, CC, FF, false);
        prop_kernel<<<NN, 128>>>(pT, br, pGr);
        launch_gemm(pXp, Wh, pT, NN, CC, FF, false);
        prop_kernel<<<NN, 128>>>(pT, bh, pGh);

        // Z = sigmoid([Gz, H] @ Lz_w + Lz_b)  (split K=1024 into two K=512 GEMMs)
        launch_gemm(pGz, Lz_w, pZ, NN, CC, CC, false);
        launch_gemm(pH, Lz_w + (size_t)CC * CC, pZ, NN, CC, CC, true);
        sigmoid_bias_kernel<<<gNC, 256>>>(pZ, Lz_b);

        // R = sigmoid([Gr, H] @ Lr_w + Lr_b)
        launch_gemm(pGr, Lr_w, pR, NN, CC, CC, false);
        launch_gemm(pH, Lr_w + (size_t)CC * CC, pR, NN, CC, CC, true);
        sigmoid_bias_kernel<<<gNC, 256>>>(pR, Lr_b);

        // R <- H * R
        hadamard_kernel<<<gNC, 256>>>(pR, pH);

        // Ht = tanh([Gh, H*R] @ Lh_w + Lh_b)
        launch_gemm(pGh, Lh_w, pHt, NN, CC, CC, false);
        launch_gemm(pR, Lh_w + (size_t)CC * CC, pHt, NN, CC, CC, true);
        tanh_bias_kernel<<<gNC, 256>>>(pHt, Lh_b);

        // Hacc += probs[p] * (Z*H + (1-Z)*Ht)
        gru_acc_kernel<<<gNC, 256>>>(pZ, pH, pHt, pHacc, p);
    }

    // head: out_hidden = Hacc ; h = relu(Hacc) @ lin1 -> relu -> @ lin2
    relu_copy_kernel<<<gNC, 256>>>(pHacc, pBA);
    launch_gemm(pBA, lin1w, phid1, NN, HIDN, CC, false);
    relu_bias_kernel<<<(NN * HIDN + 255) / 256, 256>>>(phid1, lin1b);
    lin2_kernel<<<(NN + 7) / 8, 256>>>(phid1, lin2w, lin2b, out);
    copy_hidden_kernel<<<(NN * C4 + 255) / 256, 256>>>(pHacc, out);
}

// round 4
// speedup vs baseline: 2.2035x; 1.9861x over previous
#include <cuda_runtime.h>
#include <cuda_bf16.h>
#include <stdint.h>
#include <math.h>

#define NN 10000
#define FF 128
#define PP 4
#define EE 160000
#define CC 512
#define HIDN 256
#define C4 (CC/4)

// ---------------- scratch (static device memory; no allocations) ----------------
__device__ float g_deg[NN];
__device__ float g_dinv[NN];
__device__ float g_normself[NN];
__device__ int   g_counts[NN];
__device__ int   g_rowptr[NN + 1];
__device__ int   g_cursor[NN];
__device__ int   g_csrsrc[EE];
__device__ float g_csrnorm[EE];
__device__ float g_probs[PP];

// fp32 buffers
__device__ float g_T[NN * CC];
__device__ float g_H[NN * CC];
__device__ float g_Z[NN * CC];
__device__ float g_R[NN * CC];
__device__ float g_Ht[NN * CC];
__device__ float g_Hacc[NN * CC];
__device__ float g_hid1[NN * HIDN];

// bf16 hi/lo activation planes (GEMM A operands)
__device__ __nv_bfloat16 g_Xh[NN * FF],  g_Xl[NN * FF];
__device__ __nv_bfloat16 g_BAh[NN * CC], g_BAl[NN * CC];
__device__ __nv_bfloat16 g_BBh[NN * CC], g_BBl[NN * CC];
__device__ __nv_bfloat16 g_Hh[NN * CC],  g_Hl[NN * CC];
__device__ __nv_bfloat16 g_Gzh[NN * CC], g_Gzl[NN * CC];
__device__ __nv_bfloat16 g_Grh[NN * CC], g_Grl[NN * CC];
__device__ __nv_bfloat16 g_Ghh[NN * CC], g_Ghl[NN * CC];
__device__ __nv_bfloat16 g_Rmh[NN * CC], g_Rml[NN * CC];
__device__ __nv_bfloat16 g_RAh[NN * CC], g_RAl[NN * CC];

// transposed+split weights [N][K] bf16 hi/lo
__device__ __nv_bfloat16 g_W1h[CC * FF], g_W1l[CC * FF];
__device__ __nv_bfloat16 g_W2h[CC * CC], g_W2l[CC * CC];
__device__ __nv_bfloat16 g_W3h[CC * CC], g_W3l[CC * CC];
__device__ __nv_bfloat16 g_W4h[CC * CC], g_W4l[CC * CC];
__device__ __nv_bfloat16 g_W5h[CC * CC], g_W5l[CC * CC];
__device__ __nv_bfloat16 g_Wzh[CC * FF], g_Wzl[CC * FF];
__device__ __nv_bfloat16 g_Wrh[CC * FF], g_Wrl[CC * FF];
__device__ __nv_bfloat16 g_Whh[CC * FF], g_Whl[CC * FF];
__device__ __nv_bfloat16 g_Lz1h[CC * CC], g_Lz1l[CC * CC];
__device__ __nv_bfloat16 g_Lz2h[CC * CC], g_Lz2l[CC * CC];
__device__ __nv_bfloat16 g_Lr1h[CC * CC], g_Lr1l[CC * CC];
__device__ __nv_bfloat16 g_Lr2h[CC * CC], g_Lr2l[CC * CC];
__device__ __nv_bfloat16 g_Lh1h[CC * CC], g_Lh1l[CC * CC];
__device__ __nv_bfloat16 g_Lh2h[CC * CC], g_Lh2l[CC * CC];
__device__ __nv_bfloat16 g_L1th[HIDN * CC], g_L1tl[HIDN * CC];

__device__ __forceinline__ void split_bf(float x, __nv_bfloat16& h, __nv_bfloat16& l) {
    h = __float2bfloat16(x);
    l = __float2bfloat16(x - __bfloat162float(h));
}
__device__ __forceinline__ uint32_t pack_bf2(__nv_bfloat16 a, __nv_bfloat16 b) {
    __nv_bfloat162 t(a, b);
    return *(uint32_t*)&t;
}

// ---------------- graph setup kernels ----------------
__global__ void init_node_arrays() {
    int i = blockIdx.x * blockDim.x + threadIdx.x;
    if (i < NN) { g_deg[i] = 0.0f; g_counts[i] = 0; g_cursor[i] = 0; }
}

__global__ void deg_edges_kernel(const int* __restrict__ ei, const float* __restrict__ ea) {
    int e = blockIdx.x * blockDim.x + threadIdx.x;
    if (e < EE) {
        int dst = ei[EE + e];
        atomicAdd(&g_deg[dst], ea[e]);
        atomicAdd(&g_counts[dst], 1);
    }
}

__global__ void deg_finalize_kernel() {
    int i = blockIdx.x * blockDim.x + threadIdx.x;
    if (i < NN) {
        float d = g_deg[i] + 1.0f;
        float di = (d > 0.0f) ? rsqrtf(d) : 0.0f;
        g_dinv[i] = di;
        g_normself[i] = di * di;
    }
}

__global__ void scan_kernel() {
    __shared__ int part[1024];
    const int per = 10;
    int t = threadIdx.x;
    int base = t * per;
    int loc[per];
    int s = 0;
#pragma unroll
    for (int i = 0; i < per; i++) {
        int idx = base + i;
        int v = (idx < NN) ? g_counts[idx] : 0;
        loc[i] = s; s += v;
    }
    part[t] = s;
    __syncthreads();
    for (int off = 1; off < 1024; off <<= 1) {
        int v = (t >= off) ? part[t - off] : 0;
        __syncthreads();
        part[t] += v;
        __syncthreads();
    }
    int offb = (t == 0) ? 0 : part[t - 1];
#pragma unroll
    for (int i = 0; i < per; i++) {
        int idx = base + i;
        if (idx < NN) g_rowptr[idx] = offb + loc[i];
    }
    if (t == 1023) g_rowptr[NN] = part[1023];
}

__global__ void scatter_kernel(const int* __restrict__ ei, const float* __restrict__ ea) {
    int e = blockIdx.x * blockDim.x + threadIdx.x;
    if (e < EE) {
        int src = ei[e];
        int dst = ei[EE + e];
        float nv = g_dinv[src] * ea[e] * g_dinv[dst];
        int pos = atomicAdd(&g_cursor[dst], 1);
        int slot = g_rowptr[dst] + pos;
        g_csrsrc[slot] = src;
        g_csrnorm[slot] = nv;
    }
}

__global__ void softmax4_kernel(const float* __restrict__ attn) {
    if (threadIdx.x == 0 && blockIdx.x == 0) {
        float m = attn[0];
        for (int p = 1; p < PP; p++) m = fmaxf(m, attn[p]);
        float s = 0.0f, e[PP];
        for (int p = 0; p < PP; p++) { e[p] = expf(attn[p] - m); s += e[p]; }
        for (int p = 0; p < PP; p++) g_probs[p] = e[p] / s;
    }
}

// weight transpose+split: out[n*Kb + k] = split(Wsrc[(k0+k)*N + n])
__global__ void wt_split_kernel(const float* __restrict__ W, int k0, int N, int Kb,
                                __nv_bfloat16* __restrict__ oh, __nv_bfloat16* __restrict__ ol) {
    int idx = blockIdx.x * blockDim.x + threadIdx.x;
    if (idx < N * Kb) {
        int n = idx / Kb;
        int k = idx - n * Kb;
        float v = W[(size_t)(k0 + k) * N + n];
        __nv_bfloat16 h, l;
        split_bf(v, h, l);
        oh[idx] = h; ol[idx] = l;
    }
}

// ---------------- bf16x3 tensor-core GEMM (pre-split operands) ----------------
// C[M,N] = A[M,K] @ B^T where Bt is [N][K] bf16 (pre-transposed weights).
// Block 128x64, BK=32, 8 warps (4M x 2N), warp tile 32x32, double buffered.
#define BM 128
#define BN 64
#define BKC 32
#define TSTR 40                      /* bf16 units per row incl. pad */
#define A_SZ (BM * TSTR)             /* 5120 el */
#define B_SZ (BN * TSTR)             /* 2560 el */
#define STG  (2 * A_SZ + 2 * B_SZ)   /* 15360 el per stage */
#define SMEM_BYTES (2 * STG * 2)     /* 61440 bytes */

// EPI: 0 = store; 2 = sigmoid(Cold + acc + bias); 3 = tanh(Cold + acc + bias); 4 = relu(acc + bias)
__device__ __forceinline__ void mma16816(float* c, const uint32_t* a, const uint32_t* b) {
    asm volatile(
        "mma.sync.aligned.m16n8k16.row.col.f32.bf16.bf16.f32 "
        "{%0,%1,%2,%3}, {%4,%5,%6,%7}, {%8,%9}, {%0,%1,%2,%3};"
        : "+f"(c[0]), "+f"(c[1]), "+f"(c[2]), "+f"(c[3])
        : "r"(a[0]), "r"(a[1]), "r"(a[2]), "r"(a[3]), "r"(b[0]), "r"(b[1]));
}

template <int EPI>
__global__ void __launch_bounds__(256) bf3_gemm(
    const __nv_bfloat16* __restrict__ Ah, const __nv_bfloat16* __restrict__ Al,
    const __nv_bfloat16* __restrict__ Bh, const __nv_bfloat16* __restrict__ Bl,
    float* __restrict__ Cm, const float* __restrict__ bias,
    int M, int N, int K) {
    extern __shared__ __align__(16) __nv_bfloat16 sm[];

    int tid = threadIdx.x;
    int m0 = blockIdx.y * BM;
    int n0 = blockIdx.x * BN;
    int warp = tid >> 5, lane = tid & 31;
    int wm = warp >> 1, wn = warp & 1;
    int g = lane >> 2, tg = lane & 3;

    float c[2][4][4];
#pragma unroll
    for (int mt = 0; mt < 2; mt++)
#pragma unroll
        for (int nt = 0; nt < 4; nt++)
#pragma unroll
            for (int i = 0; i < 4; i++) c[mt][nt][i] = 0.0f;

    // A tile: 128 rows x 32 bf16 = 512 uint4 per plane; 2/thread/plane
    int a_r0 = tid >> 2, a_q0 = tid & 3;
    int a_r1 = (tid + 256) >> 2, a_q1 = (tid + 256) & 3;
    // B tile: 64 rows x 32 bf16 = 256 uint4 per plane; 1/thread/plane
    int b_n = tid >> 2, b_q = tid & 3;

    uint4 rAh[2], rAl[2], rBh, rBl;
    const uint4 z4 = make_uint4(0u, 0u, 0u, 0u);

    auto load_glb = [&](int k0) {
        int m = m0 + a_r0;
        size_t off = (size_t)m * K + k0 + a_q0 * 8;
        rAh[0] = (m < M) ? *(const uint4*)(Ah + off) : z4;
        rAl[0] = (m < M) ? *(const uint4*)(Al + off) : z4;
        m = m0 + a_r1;
        off = (size_t)m * K + k0 + a_q1 * 8;
        rAh[1] = (m < M) ? *(const uint4*)(Ah + off) : z4;
        rAl[1] = (m < M) ? *(const uint4*)(Al + off) : z4;
        size_t boff = (size_t)(n0 + b_n) * K + k0 + b_q * 8;
        rBh = *(const uint4*)(Bh + boff);
        rBl = *(const uint4*)(Bl + boff);
    };

    auto store_smem = [&](int st) {
        __nv_bfloat16* Ahs = sm + st * STG;
        __nv_bfloat16* Als = Ahs + A_SZ;
        __nv_bfloat16* Bhs = Als + A_SZ;
        __nv_bfloat16* Bls = Bhs + B_SZ;
        *(uint4*)(Ahs + a_r0 * TSTR + a_q0 * 8) = rAh[0];
        *(uint4*)(Ahs + a_r1 * TSTR + a_q1 * 8) = rAh[1];
        *(uint4*)(Als + a_r0 * TSTR + a_q0 * 8) = rAl[0];
        *(uint4*)(Als + a_r1 * TSTR + a_q1 * 8) = rAl[1];
        *(uint4*)(Bhs + b_n * TSTR + b_q * 8) = rBh;
        *(uint4*)(Bls + b_n * TSTR + b_q * 8) = rBl;
    };

    auto compute = [&](int st) {
        const __nv_bfloat16* Ahs = sm + st * STG;
        const __nv_bfloat16* Als = Ahs + A_SZ;
        const __nv_bfloat16* Bhs = Als + A_SZ;
        const __nv_bfloat16* Bls = Bhs + B_SZ;
#pragma unroll
        for (int ks = 0; ks < 2; ks++) {
            int kb = ks * 16 + tg * 2;
            uint32_t af[2][2][4];
#pragma unroll
            for (int mt = 0; mt < 2; mt++) {
                int rb = wm * 32 + mt * 16;
                const __nv_bfloat16* p0 = Ahs + (rb + g) * TSTR + kb;
                const __nv_bfloat16* p1 = Als + (rb + g) * TSTR + kb;
                af[mt][0][0] = *(const uint32_t*)p0;
                af[mt][0][1] = *(const uint32_t*)(p0 + 8 * TSTR);
                af[mt][0][2] = *(const uint32_t*)(p0 + 8);
                af[mt][0][3] = *(const uint32_t*)(p0 + 8 * TSTR + 8);
                af[mt][1][0] = *(const uint32_t*)p1;
                af[mt][1][1] = *(const uint32_t*)(p1 + 8 * TSTR);
                af[mt][1][2] = *(const uint32_t*)(p1 + 8);
                af[mt][1][3] = *(const uint32_t*)(p1 + 8 * TSTR + 8);
            }
            uint32_t bfr[4][2][2];
#pragma unroll
            for (int nt = 0; nt < 4; nt++) {
                int nb = wn * 32 + nt * 8 + g;
                const __nv_bfloat16* q0 = Bhs + nb * TSTR + kb;
                const __nv_bfloat16* q1 = Bls + nb * TSTR + kb;
                bfr[nt][0][0] = *(const uint32_t*)q0;
                bfr[nt][0][1] = *(const uint32_t*)(q0 + 8);
                bfr[nt][1][0] = *(const uint32_t*)q1;
                bfr[nt][1][1] = *(const uint32_t*)(q1 + 8);
            }
#pragma unroll
            for (int mt = 0; mt < 2; mt++)
#pragma unroll
                for (int nt = 0; nt < 4; nt++) {
                    mma16816(c[mt][nt], af[mt][0], bfr[nt][0]);  // hi*hi
                    mma16816(c[mt][nt], af[mt][1], bfr[nt][0]);  // lo*hi
                    mma16816(c[mt][nt], af[mt][0], bfr[nt][1]);  // hi*lo
                }
        }
    };

    int nchunks = K / BKC;
    load_glb(0);
    store_smem(0);
    __syncthreads();
    for (int ch = 0; ch < nchunks; ch++) {
        int st = ch & 1;
        if (ch + 1 < nchunks) load_glb((ch + 1) * BKC);
        compute(st);
        if (ch + 1 < nchunks) store_smem(st ^ 1);
        __syncthreads();
    }

    // epilogue
#pragma unroll
    for (int mt = 0; mt < 2; mt++) {
#pragma unroll
        for (int nt = 0; nt < 4; nt++) {
            int col = n0 + wn * 32 + nt * 8 + tg * 2;
            float bv0 = 0.f, bv1 = 0.f;
            if (EPI >= 2) { bv0 = __ldg(&bias[col]); bv1 = __ldg(&bias[col + 1]); }
#pragma unroll
            for (int half = 0; half < 2; half++) {
                int row = m0 + wm * 32 + mt * 16 + g + half * 8;
                if (row >= M) continue;
                float v0 = c[mt][nt][half * 2 + 0];
                float v1 = c[mt][nt][half * 2 + 1];
                float* cp = &Cm[(size_t)row * N + col];
                if (EPI == 0) {
                    *(float2*)cp = make_float2(v0, v1);
                } else if (EPI == 2) {
                    float2 old = *(float2*)cp;
                    float a0 = old.x + v0 + bv0, a1 = old.y + v1 + bv1;
                    *(float2*)cp = make_float2(1.0f / (1.0f + expf(-a0)),
                                               1.0f / (1.0f + expf(-a1)));
                } else if (EPI == 3) {
                    float2 old = *(float2*)cp;
                    *(float2*)cp = make_float2(tanhf(old.x + v0 + bv0),
                                               tanhf(old.y + v1 + bv1));
                } else {  // EPI == 4: relu(acc + bias)
                    *(float2*)cp = make_float2(fmaxf(v0 + bv0, 0.0f),
                                               fmaxf(v1 + bv1, 0.0f));
                }
            }
        }
    }
}

// ---------------- GCN propagation with fused bf16 split emission ----------------
template <bool WF32>
__global__ void __launch_bounds__(128) prop_split_kernel(
    const float* __restrict__ T, const float* __restrict__ bias,
    float* __restrict__ outf,
    __nv_bfloat16* __restrict__ oh, __nv_bfloat16* __restrict__ ol) {
    int i = blockIdx.x;
    int t = threadIdx.x;
    const float4* T4 = (const float4*)T;
    float4 b = ((const float4*)bias)[t];
    float sn = g_normself[i];
    float4 v = T4[(size_t)i * C4 + t];
    float4 acc = make_float4(b.x + sn * v.x, b.y + sn * v.y, b.z + sn * v.z, b.w + sn * v.w);
    int beg = g_rowptr[i];
    int end = g_rowptr[i + 1];
    for (int e = beg; e < end; e++) {
        int s = g_csrsrc[e];
        float w = g_csrnorm[e];
        float4 u = T4[(size_t)s * C4 + t];
        acc.x = fmaf(w, u.x, acc.x);
        acc.y = fmaf(w, u.y, acc.y);
        acc.z = fmaf(w, u.z, acc.z);
        acc.w = fmaf(w, u.w, acc.w);
    }
    if (WF32) ((float4*)outf)[(size_t)i * C4 + t] = acc;
    __nv_bfloat16 h0, h1, h2, h3, l0, l1, l2, l3;
    split_bf(acc.x, h0, l0); split_bf(acc.y, h1, l1);
    split_bf(acc.z, h2, l2); split_bf(acc.w, h3, l3);
    size_t off = (size_t)i * CC + t * 4;
    *(uint2*)(oh + off) = make_uint2(pack_bf2(h0, h1), pack_bf2(h2, h3));
    *(uint2*)(ol + off) = make_uint2(pack_bf2(l0, l1), pack_bf2(l2, l3));
}

// ---------------- elementwise kernels ----------------
__global__ void extract_split_kernel(const float* __restrict__ x, int p,
                                     __nv_bfloat16* __restrict__ oh,
                                     __nv_bfloat16* __restrict__ ol) {
    int idx = blockIdx.x * blockDim.x + threadIdx.x;
    if (idx < NN * FF) {
        float v = x[(size_t)idx * PP + p];
        __nv_bfloat16 h, l;
        split_bf(v, h, l);
        oh[idx] = h; ol[idx] = l;
    }
}

__global__ void zero_f_kernel(float* __restrict__ a, int n) {
    int idx = blockIdx.x * blockDim.x + threadIdx.x;
    if (idx < n) a[idx] = 0.0f;
}

// Rm = H * R, split to bf16 planes
__global__ void hadamard_split_kernel(const float* __restrict__ R, const float* __restrict__ H,
                                      __nv_bfloat16* __restrict__ oh,
                                      __nv_bfloat16* __restrict__ ol) {
    int idx = blockIdx.x * blockDim.x + threadIdx.x;
    if (idx < NN * C4) {
        float4 r = ((const float4*)R)[idx];
        float4 h = ((const float4*)H)[idx];
        float4 m = make_float4(r.x * h.x, r.y * h.y, r.z * h.z, r.w * h.w);
        __nv_bfloat16 h0, h1, h2, h3, l0, l1, l2, l3;
        split_bf(m.x, h0, l0); split_bf(m.y, h1, l1);
        split_bf(m.z, h2, l2); split_bf(m.w, h3, l3);
        *(uint2*)(oh + (size_t)idx * 4) = make_uint2(pack_bf2(h0, h1), pack_bf2(h2, h3));
        *(uint2*)(ol + (size_t)idx * 4) = make_uint2(pack_bf2(l0, l1), pack_bf2(l2, l3));
    }
}

__global__ void gru_acc_kernel(const float* __restrict__ Z, const float* __restrict__ H,
                               const float* __restrict__ Ht, float* __restrict__ Hacc, int p) {
    int idx = blockIdx.x * blockDim.x + threadIdx.x;
    if (idx < NN * CC) {
        float pr = g_probs[p];
        float z = Z[idx];
        float hn = z * H[idx] + (1.0f - z) * Ht[idx];
        Hacc[idx] += pr * hn;
    }
}

// relu + split (for final MLP input)
__global__ void relu_split_kernel(const float* __restrict__ src,
                                  __nv_bfloat16* __restrict__ oh,
                                  __nv_bfloat16* __restrict__ ol) {
    int idx = blockIdx.x * blockDim.x + threadIdx.x;
    if (idx < NN * C4) {
        float4 v = ((const float4*)src)[idx];
        v.x = fmaxf(v.x, 0.f); v.y = fmaxf(v.y, 0.f);
        v.z = fmaxf(v.z, 0.f); v.w = fmaxf(v.w, 0.f);
        __nv_bfloat16 h0, h1, h2, h3, l0, l1, l2, l3;
        split_bf(v.x, h0, l0); split_bf(v.y, h1, l1);
        split_bf(v.z, h2, l2); split_bf(v.w, h3, l3);
        *(uint2*)(oh + (size_t)idx * 4) = make_uint2(pack_bf2(h0, h1), pack_bf2(h2, h3));
        *(uint2*)(ol + (size_t)idx * 4) = make_uint2(pack_bf2(l0, l1), pack_bf2(l2, l3));
    }
}

// final 256->1 projection
__global__ void lin2_kernel(const float* __restrict__ hid, const float* __restrict__ w,
                            const float* __restrict__ b, float* __restrict__ out) {
    int n = blockIdx.x * 8 + (threadIdx.x >> 5);
    int lane = threadIdx.x & 31;
    float s = 0.0f;
    for (int k = lane; k < HIDN; k += 32) s = fmaf(hid[(size_t)n * HIDN + k], w[k], s);
#pragma unroll
    for (int off = 16; off; off >>= 1) s += __shfl_down_sync(0xffffffffu, s, off);
    if (lane == 0) out[n] = s + b[0];
}

__global__ void copy_hidden_kernel(const float* __restrict__ Hacc, float* __restrict__ out) {
    int idx = blockIdx.x * blockDim.x + threadIdx.x;
    if (idx < NN * C4) {
        ((float4*)(out + NN))[idx] = ((const float4*)Hacc)[idx];
    }
}

// ---------------- host orchestration ----------------
#define GP(sym) ({ void* _p; cudaGetSymbolAddress(&_p, sym); (__nv_bfloat16*)_p; })
#define GPF(sym) ({ void* _p; cudaGetSymbolAddress(&_p, sym); (float*)_p; })

static inline void launch_gemm0(const __nv_bfloat16* Ah, const __nv_bfloat16* Al,
                                const __nv_bfloat16* Bh, const __nv_bfloat16* Bl,
                                float* C, int M, int N, int K) {
    dim3 grid(N / BN, (M + BM - 1) / BM);
    bf3_gemm<0><<<grid, 256, SMEM_BYTES>>>(Ah, Al, Bh, Bl, C, nullptr, M, N, K);
}
template <int EPI>
static inline void launch_gemmE(const __nv_bfloat16* Ah, const __nv_bfloat16* Al,
                                const __nv_bfloat16* Bh, const __nv_bfloat16* Bl,
                                float* C, const float* bias, int M, int N, int K) {
    dim3 grid(N / BN, (M + BM - 1) / BM);
    bf3_gemm<EPI><<<grid, 256, SMEM_BYTES>>>(Ah, Al, Bh, Bl, C, bias, M, N, K);
}

extern "C" void kernel_launch(void* const* d_in, const int* in_sizes, int n_in,
                              void* d_out, int out_size) {
    const float* x     = (const float*)d_in[0];
    const int*   ei    = (const int*)d_in[1];
    const float* ea    = (const float*)d_in[2];
    const float* W1    = (const float*)d_in[3];
    const float* b1    = (const float*)d_in[4];
    const float* W2    = (const float*)d_in[5];
    const float* b2    = (const float*)d_in[6];
    const float* W3    = (const float*)d_in[7];
    const float* b3    = (const float*)d_in[8];
    const float* W4    = (const float*)d_in[9];
    const float* b4    = (const float*)d_in[10];
    const float* W5    = (const float*)d_in[11];
    const float* b5    = (const float*)d_in[12];
    const float* Wz    = (const float*)d_in[13];
    const float* bz    = (const float*)d_in[14];
    const float* Lz_w  = (const float*)d_in[15];
    const float* Lz_b  = (const float*)d_in[16];
    const float* Wr    = (const float*)d_in[17];
    const float* br    = (const float*)d_in[18];
    const float* Lr_w  = (const float*)d_in[19];
    const float* Lr_b  = (const float*)d_in[20];
    const float* Wh    = (const float*)d_in[21];
    const float* bh    = (const float*)d_in[22];
    const float* Lh_w  = (const float*)d_in[23];
    const float* Lh_b  = (const float*)d_in[24];
    const float* attn  = (const float*)d_in[25];
    const float* lin1w = (const float*)d_in[26];
    const float* lin1b = (const float*)d_in[27];
    const float* lin2w = (const float*)d_in[28];
    const float* lin2b = (const float*)d_in[29];
    float* out = (float*)d_out;

    static bool attr_done = false;
    if (!attr_done) {
        cudaFuncSetAttribute(bf3_gemm<0>, cudaFuncAttributeMaxDynamicSharedMemorySize, SMEM_BYTES);
        cudaFuncSetAttribute(bf3_gemm<2>, cudaFuncAttributeMaxDynamicSharedMemorySize, SMEM_BYTES);
        cudaFuncSetAttribute(bf3_gemm<3>, cudaFuncAttributeMaxDynamicSharedMemorySize, SMEM_BYTES);
        cudaFuncSetAttribute(bf3_gemm<4>, cudaFuncAttributeMaxDynamicSharedMemorySize, SMEM_BYTES);
        attr_done = true;
    }

    float* pT    = GPF(g_T);
    float* pH    = GPF(g_H);
    float* pZ    = GPF(g_Z);
    float* pR    = GPF(g_R);
    float* pHt   = GPF(g_Ht);
    float* pHacc = GPF(g_Hacc);
    float* phid1 = GPF(g_hid1);

    __nv_bfloat16 *pXh = GP(g_Xh), *pXl = GP(g_Xl);
    __nv_bfloat16 *pBAh = GP(g_BAh), *pBAl = GP(g_BAl);
    __nv_bfloat16 *pBBh = GP(g_BBh), *pBBl = GP(g_BBl);
    __nv_bfloat16 *pHh = GP(g_Hh), *pHl = GP(g_Hl);
    __nv_bfloat16 *pGzh = GP(g_Gzh), *pGzl = GP(g_Gzl);
    __nv_bfloat16 *pGrh = GP(g_Grh), *pGrl = GP(g_Grl);
    __nv_bfloat16 *pGhh = GP(g_Ghh), *pGhl = GP(g_Ghl);
    __nv_bfloat16 *pRmh = GP(g_Rmh), *pRml = GP(g_Rml);
    __nv_bfloat16 *pRAh = GP(g_RAh), *pRAl = GP(g_RAl);

    __nv_bfloat16 *pW1h = GP(g_W1h), *pW1l = GP(g_W1l);
    __nv_bfloat16 *pW2h = GP(g_W2h), *pW2l = GP(g_W2l);
    __nv_bfloat16 *pW3h = GP(g_W3h), *pW3l = GP(g_W3l);
    __nv_bfloat16 *pW4h = GP(g_W4h), *pW4l = GP(g_W4l);
    __nv_bfloat16 *pW5h = GP(g_W5h), *pW5l = GP(g_W5l);
    __nv_bfloat16 *pWzh = GP(g_Wzh), *pWzl = GP(g_Wzl);
    __nv_bfloat16 *pWrh = GP(g_Wrh), *pWrl = GP(g_Wrl);
    __nv_bfloat16 *pWhh = GP(g_Whh), *pWhl = GP(g_Whl);
    __nv_bfloat16 *pLz1h = GP(g_Lz1h), *pLz1l = GP(g_Lz1l);
    __nv_bfloat16 *pLz2h = GP(g_Lz2h), *pLz2l = GP(g_Lz2l);
    __nv_bfloat16 *pLr1h = GP(g_Lr1h), *pLr1l = GP(g_Lr1l);
    __nv_bfloat16 *pLr2h = GP(g_Lr2h), *pLr2l = GP(g_Lr2l);
    __nv_bfloat16 *pLh1h = GP(g_Lh1h), *pLh1l = GP(g_Lh1l);
    __nv_bfloat16 *pLh2h = GP(g_Lh2h), *pLh2l = GP(g_Lh2l);
    __nv_bfloat16 *pL1th = GP(g_L1th), *pL1tl = GP(g_L1tl);

    const int gE  = (EE + 255) / 256;
    const int gN  = (NN + 255) / 256;
    const int gNC = (NN * CC + 255) / 256;
    const int gNC4 = (NN * C4 + 255) / 256;
    const int gNF = (NN * FF + 255) / 256;
    const int gW512 = (CC * CC + 255) / 256;
    const int gW128 = (CC * FF + 255) / 256;
    const int gWL1 = (HIDN * CC + 255) / 256;

    // graph setup + CSR
    init_node_arrays<<<gN, 256>>>();
    deg_edges_kernel<<<gE, 256>>>(ei, ea);
    deg_finalize_kernel<<<gN, 256>>>();
    scan_kernel<<<1, 1024>>>();
    scatter_kernel<<<gE, 256>>>(ei, ea);
    softmax4_kernel<<<1, 32>>>(attn);
    zero_f_kernel<<<gNC, 256>>>(pHacc, NN * CC);

    // weight transpose + split
    wt_split_kernel<<<gW128, 256>>>(W1, 0, CC, FF, pW1h, pW1l);
    wt_split_kernel<<<gW512, 256>>>(W2, 0, CC, CC, pW2h, pW2l);
    wt_split_kernel<<<gW512, 256>>>(W3, 0, CC, CC, pW3h, pW3l);
    wt_split_kernel<<<gW512, 256>>>(W4, 0, CC, CC, pW4h, pW4l);
    wt_split_kernel<<<gW512, 256>>>(W5, 0, CC, CC, pW5h, pW5l);
    wt_split_kernel<<<gW128, 256>>>(Wz, 0, CC, FF, pWzh, pWzl);
    wt_split_kernel<<<gW128, 256>>>(Wr, 0, CC, FF, pWrh, pWrl);
    wt_split_kernel<<<gW128, 256>>>(Wh, 0, CC, FF, pWhh, pWhl);
    wt_split_kernel<<<gW512, 256>>>(Lz_w, 0, CC, CC, pLz1h, pLz1l);
    wt_split_kernel<<<gW512, 256>>>(Lz_w, CC, CC, CC, pLz2h, pLz2l);
    wt_split_kernel<<<gW512, 256>>>(Lr_w, 0, CC, CC, pLr1h, pLr1l);
    wt_split_kernel<<<gW512, 256>>>(Lr_w, CC, CC, CC, pLr2h, pLr2l);
    wt_split_kernel<<<gW512, 256>>>(Lh_w, 0, CC, CC, pLh1h, pLh1l);
    wt_split_kernel<<<gW512, 256>>>(Lh_w, CC, CC, CC, pLh2h, pLh2l);
    wt_split_kernel<<<gWL1, 256>>>(lin1w, 0, HIDN, CC, pL1th, pL1tl);

    for (int p = 0; p < PP; p++) {
        extract_split_kernel<<<gNF, 256>>>(x, p, pXh, pXl);

        // 5-layer GCN chain
        launch_gemm0(pXh, pXl, pW1h, pW1l, pT, NN, CC, FF);
        prop_split_kernel<false><<<NN, 128>>>(pT, b1, nullptr, pBAh, pBAl);
        launch_gemm0(pBAh, pBAl, pW2h, pW2l, pT, NN, CC, CC);
        prop_split_kernel<false><<<NN, 128>>>(pT, b2, nullptr, pBBh, pBBl);
        launch_gemm0(pBBh, pBBl, pW3h, pW3l, pT, NN, CC, CC);
        prop_split_kernel<false><<<NN, 128>>>(pT, b3, nullptr, pBAh, pBAl);
        launch_gemm0(pBAh, pBAl, pW4h, pW4l, pT, NN, CC, CC);
        prop_split_kernel<false><<<NN, 128>>>(pT, b4, nullptr, pBBh, pBBl);
        launch_gemm0(pBBh, pBBl, pW5h, pW5l, pT, NN, CC, CC);
        prop_split_kernel<true><<<NN, 128>>>(pT, b5, pH, pHh, pHl);

        // gate inputs
        launch_gemm0(pXh, pXl, pWzh, pWzl, pT, NN, CC, FF);
        prop_split_kernel<false><<<NN, 128>>>(pT, bz, nullptr, pGzh, pGzl);
        launch_gemm0(pXh, pXl, pWrh, pWrl, pT, NN, CC, FF);
        prop_split_kernel<false><<<NN, 128>>>(pT, br, nullptr, pGrh, pGrl);
        launch_gemm0(pXh, pXl, pWhh, pWhl, pT, NN, CC, FF);
        prop_split_kernel<false><<<NN, 128>>>(pT, bh, nullptr, pGhh, pGhl);

        // Z = sigmoid(Gz@Lz1 + H@Lz2 + bias)
        launch_gemm0(pGzh, pGzl, pLz1h, pLz1l, pZ, NN, CC, CC);
        launch_gemmE<2>(pHh, pHl, pLz2h, pLz2l, pZ, Lz_b, NN, CC, CC);

        // R = sigmoid(Gr@Lr1 + H@Lr2 + bias)
        launch_gemm0(pGrh, pGrl, pLr1h, pLr1l, pR, NN, CC, CC);
        launch_gemmE<2>(pHh, pHl, pLr2h, pLr2l, pR, Lr_b, NN, CC, CC);

        // Rm = H * R (split)
        hadamard_split_kernel<<<gNC4, 256>>>(pR, pH, pRmh, pRml);

        // Ht = tanh(Gh@Lh1 + Rm@Lh2 + bias)
        launch_gemm0(pGhh, pGhl, pLh1h, pLh1l, pHt, NN, CC, CC);
        launch_gemmE<3>(pRmh, pRml, pLh2h, pLh2l, pHt, Lh_b, NN, CC, CC);

        // Hacc += probs[p] * (Z*H + (1-Z)*Ht)
        gru_acc_kernel<<<gNC, 256>>>(pZ, pH, pHt, pHacc, p);
    }

    // head
    relu_split_kernel<<<gNC4, 256>>>(pHacc, pRAh, pRAl);
    launch_gemmE<4>(pRAh, pRAl, pL1th, pL1tl, phid1, lin1b, NN, HIDN, CC);
    lin2_kernel<<<(NN + 7) / 8, 256>>>(phid1, lin2w, lin2b, out);
    copy_hidden_kernel<<<gNC4, 256>>>(pHacc, out);
}

// round 5
// speedup vs baseline: 3.1038x; 1.4086x over previous
#include <cuda_runtime.h>
#include <cuda_bf16.h>
#include <stdint.h>
#include <math.h>

#define NN 10000
#define FF 128
#define PP 4
#define EE 160000
#define CC 512
#define HIDN 256
#define C4 (CC/4)
#define F4 (FF/4)

// ---------------- scratch (static device memory; no allocations) ----------------
__device__ float g_deg[NN];
__device__ float g_dinv[NN];
__device__ float g_normself[NN];
__device__ int   g_counts[NN];
__device__ int   g_rowptr[NN + 1];
__device__ int   g_cursor[NN];
__device__ int   g_csrsrc[EE];
__device__ float g_csrnorm[EE];
__device__ float g_probs[PP];

// fp32 buffers
__device__ float g_Xp[NN * FF];
__device__ float g_T[NN * CC];
__device__ float g_H[NN * CC];
__device__ float g_Z[NN * CC];
__device__ float g_Ht[NN * CC];
__device__ float g_Hacc[NN * CC];
__device__ float g_hid1[NN * HIDN];
__device__ float g_Mtmp[FF * CC];     // folded gate weight scratch (fp32)
__device__ float g_bvz[CC], g_bvr[CC], g_bvh[CC];

// bf16 hi/lo activation planes (GEMM A operands)
__device__ __nv_bfloat16 g_Xsh[NN * FF], g_Xsl[NN * FF];   // Xs = S*Xp
__device__ __nv_bfloat16 g_BAh[NN * CC], g_BAl[NN * CC];
__device__ __nv_bfloat16 g_BBh[NN * CC], g_BBl[NN * CC];
__device__ __nv_bfloat16 g_Hh[NN * CC],  g_Hl[NN * CC];
__device__ __nv_bfloat16 g_Rmh[NN * CC], g_Rml[NN * CC];
__device__ __nv_bfloat16 g_RAh[NN * CC], g_RAl[NN * CC];

// transposed+split weights [N][K] bf16 hi/lo
__device__ __nv_bfloat16 g_W1h[CC * FF], g_W1l[CC * FF];
__device__ __nv_bfloat16 g_W2h[CC * CC], g_W2l[CC * CC];
__device__ __nv_bfloat16 g_W3h[CC * CC], g_W3l[CC * CC];
__device__ __nv_bfloat16 g_W4h[CC * CC], g_W4l[CC * CC];
__device__ __nv_bfloat16 g_W5h[CC * CC], g_W5l[CC * CC];
__device__ __nv_bfloat16 g_Mzh[CC * FF], g_Mzl[CC * FF];   // (Wz@Lz1)^T
__device__ __nv_bfloat16 g_Mrh[CC * FF], g_Mrl[CC * FF];
__device__ __nv_bfloat16 g_Mhh[CC * FF], g_Mhl[CC * FF];
__device__ __nv_bfloat16 g_Lz2h[CC * CC], g_Lz2l[CC * CC];
__device__ __nv_bfloat16 g_Lr2h[CC * CC], g_Lr2l[CC * CC];
__device__ __nv_bfloat16 g_Lh2h[CC * CC], g_Lh2l[CC * CC];
__device__ __nv_bfloat16 g_L1th[HIDN * CC], g_L1tl[HIDN * CC];

__device__ __forceinline__ void split_bf(float x, __nv_bfloat16& h, __nv_bfloat16& l) {
    h = __float2bfloat16(x);
    l = __float2bfloat16(x - __bfloat162float(h));
}
__device__ __forceinline__ uint32_t pack_bf2(__nv_bfloat16 a, __nv_bfloat16 b) {
    __nv_bfloat162 t(a, b);
    return *(uint32_t*)&t;
}
__device__ __forceinline__ uint32_t split_pack(float a, float b) {
    __nv_bfloat16 h0, l0, h1, l1;
    split_bf(a, h0, l0); split_bf(b, h1, l1);
    return pack_bf2(h0, h1);
}
__device__ __forceinline__ uint32_t split_pack_lo(float a, float b) {
    __nv_bfloat16 h0, l0, h1, l1;
    split_bf(a, h0, l0); split_bf(b, h1, l1);
    return pack_bf2(l0, l1);
}

// ---------------- graph setup kernels ----------------
__global__ void init_node_arrays() {
    int i = blockIdx.x * blockDim.x + threadIdx.x;
    if (i < NN) { g_deg[i] = 0.0f; g_counts[i] = 0; g_cursor[i] = 0; }
}

__global__ void deg_edges_kernel(const int* __restrict__ ei, const float* __restrict__ ea) {
    int e = blockIdx.x * blockDim.x + threadIdx.x;
    if (e < EE) {
        int dst = ei[EE + e];
        atomicAdd(&g_deg[dst], ea[e]);
        atomicAdd(&g_counts[dst], 1);
    }
}

__global__ void deg_finalize_kernel() {
    int i = blockIdx.x * blockDim.x + threadIdx.x;
    if (i < NN) {
        float d = g_deg[i] + 1.0f;
        float di = (d > 0.0f) ? rsqrtf(d) : 0.0f;
        g_dinv[i] = di;
        g_normself[i] = di * di;
    }
}

__global__ void scan_kernel() {
    __shared__ int part[1024];
    const int per = 10;
    int t = threadIdx.x;
    int base = t * per;
    int loc[per];
    int s = 0;
#pragma unroll
    for (int i = 0; i < per; i++) {
        int idx = base + i;
        int v = (idx < NN) ? g_counts[idx] : 0;
        loc[i] = s; s += v;
    }
    part[t] = s;
    __syncthreads();
    for (int off = 1; off < 1024; off <<= 1) {
        int v = (t >= off) ? part[t - off] : 0;
        __syncthreads();
        part[t] += v;
        __syncthreads();
    }
    int offb = (t == 0) ? 0 : part[t - 1];
#pragma unroll
    for (int i = 0; i < per; i++) {
        int idx = base + i;
        if (idx < NN) g_rowptr[idx] = offb + loc[i];
    }
    if (t == 1023) g_rowptr[NN] = part[1023];
}

__global__ void scatter_kernel(const int* __restrict__ ei, const float* __restrict__ ea) {
    int e = blockIdx.x * blockDim.x + threadIdx.x;
    if (e < EE) {
        int src = ei[e];
        int dst = ei[EE + e];
        float nv = g_dinv[src] * ea[e] * g_dinv[dst];
        int pos = atomicAdd(&g_cursor[dst], 1);
        int slot = g_rowptr[dst] + pos;
        g_csrsrc[slot] = src;
        g_csrnorm[slot] = nv;
    }
}

__global__ void softmax4_kernel(const float* __restrict__ attn) {
    if (threadIdx.x == 0 && blockIdx.x == 0) {
        float m = attn[0];
        for (int p = 1; p < PP; p++) m = fmaxf(m, attn[p]);
        float s = 0.0f, e[PP];
        for (int p = 0; p < PP; p++) { e[p] = expf(attn[p] - m); s += e[p]; }
        for (int p = 0; p < PP; p++) g_probs[p] = e[p] / s;
    }
}

// weight transpose+split: out[n*Kb + k] = split(Wsrc[(k0+k)*N + n])
__global__ void wt_split_kernel(const float* __restrict__ W, int k0, int N, int Kb,
                                __nv_bfloat16* __restrict__ oh, __nv_bfloat16* __restrict__ ol) {
    int idx = blockIdx.x * blockDim.x + threadIdx.x;
    if (idx < N * Kb) {
        int n = idx / Kb;
        int k = idx - n * Kb;
        float v = W[(size_t)(k0 + k) * N + n];
        __nv_bfloat16 h, l;
        split_bf(v, h, l);
        oh[idx] = h; ol[idx] = l;
    }
}

// M[f][n] = sum_k Wsm[f][k] * Lw_top[k][n]    (fp32, small: 128x512x512)
__global__ void gatefold_kernel(const float* __restrict__ Wsm, const float* __restrict__ Lw,
                                float* __restrict__ M) {
    int idx = blockIdx.x * blockDim.x + threadIdx.x;
    if (idx < FF * CC) {
        int f = idx / CC, n = idx - f * CC;
        float s = 0.0f;
        for (int k = 0; k < CC; k++)
            s = fmaf(Wsm[(size_t)f * CC + k], Lw[(size_t)k * CC + n], s);
        M[idx] = s;
    }
}

// bv[n] = Lb[n] + sum_k bsmall[k] * Lw_top[k][n]
__global__ void gate_bias_kernel(const float* __restrict__ Lw, const float* __restrict__ Lb,
                                 const float* __restrict__ bsmall, float* __restrict__ bv) {
    int n = blockIdx.x * blockDim.x + threadIdx.x;
    if (n < CC) {
        float s = Lb[n];
        for (int k = 0; k < CC; k++)
            s = fmaf(bsmall[k], Lw[(size_t)k * CC + n], s);
        bv[n] = s;
    }
}

// ---------------- bf16x3 tensor-core GEMM (ldmatrix, pre-split operands) ----------------
#define BM 128
#define BN 64
#define BKC 32
#define TSTR 40                      /* bf16 units per row incl. pad (80B) */
#define A_SZ (BM * TSTR)
#define B_SZ (BN * TSTR)
#define STG  (2 * A_SZ + 2 * B_SZ)
#define SMEM_BYTES (2 * STG * 2)     /* 61440 bytes */

__device__ __forceinline__ void mma16816(float* c, const uint32_t* a, const uint32_t* b) {
    asm volatile(
        "mma.sync.aligned.m16n8k16.row.col.f32.bf16.bf16.f32 "
        "{%0,%1,%2,%3}, {%4,%5,%6,%7}, {%8,%9}, {%0,%1,%2,%3};"
        : "+f"(c[0]), "+f"(c[1]), "+f"(c[2]), "+f"(c[3])
        : "r"(a[0]), "r"(a[1]), "r"(a[2]), "r"(a[3]), "r"(b[0]), "r"(b[1]));
}

__device__ __forceinline__ void ldsm_x4(const void* p, uint32_t* r) {
    uint32_t addr = (uint32_t)__cvta_generic_to_shared(p);
    asm volatile("ldmatrix.sync.aligned.m8n8.x4.shared.b16 {%0,%1,%2,%3}, [%4];"
        : "=r"(r[0]), "=r"(r[1]), "=r"(r[2]), "=r"(r[3]) : "r"(addr));
}

// EPI: 0 store fp32; 1 split(acc+bias)->planes; 2 sigmoid(old+acc+bias)->fp32;
//      4 relu(acc+bias)->fp32; 5 sigmoid(old+acc+bias)*H->planes; 6 gru accumulate
template <int EPI>
__global__ void __launch_bounds__(256) bf3_gemm(
    const __nv_bfloat16* __restrict__ Ah, const __nv_bfloat16* __restrict__ Al,
    const __nv_bfloat16* __restrict__ Bh, const __nv_bfloat16* __restrict__ Bl,
    float* __restrict__ Cm, const float* __restrict__ bias,
    const float* __restrict__ Zp, const float* __restrict__ Hp,
    float* __restrict__ Hacc,
    __nv_bfloat16* __restrict__ oh, __nv_bfloat16* __restrict__ ol,
    int pidx, int M, int N, int K) {
    extern __shared__ __align__(16) __nv_bfloat16 sm[];

    int tid = threadIdx.x;
    int m0 = blockIdx.y * BM;
    int n0 = blockIdx.x * BN;
    int warp = tid >> 5, lane = tid & 31;
    int wm = warp >> 1, wn = warp & 1;
    int g = lane >> 2, tg = lane & 3;

    float c[2][4][4];
#pragma unroll
    for (int mt = 0; mt < 2; mt++)
#pragma unroll
        for (int nt = 0; nt < 4; nt++)
#pragma unroll
            for (int i = 0; i < 4; i++) c[mt][nt][i] = 0.0f;

    int a_r0 = tid >> 2, a_q0 = tid & 3;
    int a_r1 = (tid + 256) >> 2, a_q1 = (tid + 256) & 3;
    int b_n = tid >> 2, b_q = tid & 3;

    uint4 rAh[2], rAl[2], rBh, rBl;
    const uint4 z4 = make_uint4(0u, 0u, 0u, 0u);

    auto load_glb = [&](int k0) {
        int m = m0 + a_r0;
        size_t off = (size_t)m * K + k0 + a_q0 * 8;
        rAh[0] = (m < M) ? *(const uint4*)(Ah + off) : z4;
        rAl[0] = (m < M) ? *(const uint4*)(Al + off) : z4;
        m = m0 + a_r1;
        off = (size_t)m * K + k0 + a_q1 * 8;
        rAh[1] = (m < M) ? *(const uint4*)(Ah + off) : z4;
        rAl[1] = (m < M) ? *(const uint4*)(Al + off) : z4;
        size_t boff = (size_t)(n0 + b_n) * K + k0 + b_q * 8;
        rBh = *(const uint4*)(Bh + boff);
        rBl = *(const uint4*)(Bl + boff);
    };

    auto store_smem = [&](int st) {
        __nv_bfloat16* Ahs = sm + st * STG;
        __nv_bfloat16* Als = Ahs + A_SZ;
        __nv_bfloat16* Bhs = Als + A_SZ;
        __nv_bfloat16* Bls = Bhs + B_SZ;
        *(uint4*)(Ahs + a_r0 * TSTR + a_q0 * 8) = rAh[0];
        *(uint4*)(Ahs + a_r1 * TSTR + a_q1 * 8) = rAh[1];
        *(uint4*)(Als + a_r0 * TSTR + a_q0 * 8) = rAl[0];
        *(uint4*)(Als + a_r1 * TSTR + a_q1 * 8) = rAl[1];
        *(uint4*)(Bhs + b_n * TSTR + b_q * 8) = rBh;
        *(uint4*)(Bls + b_n * TSTR + b_q * 8) = rBl;
    };

    auto compute = [&](int st) {
        const __nv_bfloat16* Ahs = sm + st * STG;
        const __nv_bfloat16* Als = Ahs + A_SZ;
        const __nv_bfloat16* Bhs = Als + A_SZ;
        const __nv_bfloat16* Bls = Bhs + B_SZ;
#pragma unroll
        for (int ks = 0; ks < 2; ks++) {
            uint32_t af[2][2][4];
            int arow = (lane & 15);
            int acol = ks * 16 + (lane >> 4) * 8;
#pragma unroll
            for (int mt = 0; mt < 2; mt++) {
                int r = wm * 32 + mt * 16 + arow;
                ldsm_x4(Ahs + r * TSTR + acol, af[mt][0]);
                ldsm_x4(Als + r * TSTR + acol, af[mt][1]);
            }
            uint32_t bfr[4][2][2];
            int bm_ = lane >> 3;
            int brow_in = lane & 7;
            int bro = (bm_ >> 1) * 8 + brow_in;
            int bco = ks * 16 + (bm_ & 1) * 8;
#pragma unroll
            for (int ntp = 0; ntp < 2; ntp++) {
                int nr = wn * 32 + ntp * 16 + bro;
                uint32_t t4[4];
                ldsm_x4(Bhs + nr * TSTR + bco, t4);
                bfr[ntp * 2][0][0] = t4[0]; bfr[ntp * 2][0][1] = t4[1];
                bfr[ntp * 2 + 1][0][0] = t4[2]; bfr[ntp * 2 + 1][0][1] = t4[3];
                ldsm_x4(Bls + nr * TSTR + bco, t4);
                bfr[ntp * 2][1][0] = t4[0]; bfr[ntp * 2][1][1] = t4[1];
                bfr[ntp * 2 + 1][1][0] = t4[2]; bfr[ntp * 2 + 1][1][1] = t4[3];
            }
#pragma unroll
            for (int mt = 0; mt < 2; mt++)
#pragma unroll
                for (int nt = 0; nt < 4; nt++) {
                    mma16816(c[mt][nt], af[mt][0], bfr[nt][0]);  // hi*hi
                    mma16816(c[mt][nt], af[mt][1], bfr[nt][0]);  // lo*hi
                    mma16816(c[mt][nt], af[mt][0], bfr[nt][1]);  // hi*lo
                }
        }
    };

    int nchunks = K / BKC;
    load_glb(0);
    store_smem(0);
    __syncthreads();
    for (int ch = 0; ch < nchunks; ch++) {
        int st = ch & 1;
        if (ch + 1 < nchunks) load_glb((ch + 1) * BKC);
        compute(st);
        if (ch + 1 < nchunks) store_smem(st ^ 1);
        __syncthreads();
    }

    // epilogue
#pragma unroll
    for (int mt = 0; mt < 2; mt++) {
#pragma unroll
        for (int nt = 0; nt < 4; nt++) {
            int col = n0 + wn * 32 + nt * 8 + tg * 2;
            float bv0 = 0.f, bv1 = 0.f;
            if (EPI != 0) { bv0 = __ldg(&bias[col]); bv1 = __ldg(&bias[col + 1]); }
#pragma unroll
            for (int half = 0; half < 2; half++) {
                int row = m0 + wm * 32 + mt * 16 + g + half * 8;
                if (row >= M) continue;
                float v0 = c[mt][nt][half * 2 + 0];
                float v1 = c[mt][nt][half * 2 + 1];
                size_t off = (size_t)row * N + col;
                if (EPI == 0) {
                    *(float2*)(Cm + off) = make_float2(v0, v1);
                } else if (EPI == 1) {
                    float a0 = v0 + bv0, a1 = v1 + bv1;
                    *(uint32_t*)(oh + off) = split_pack(a0, a1);
                    *(uint32_t*)(ol + off) = split_pack_lo(a0, a1);
                } else if (EPI == 2) {
                    float2 old = *(float2*)(Cm + off);
                    float a0 = old.x + v0 + bv0, a1 = old.y + v1 + bv1;
                    *(float2*)(Cm + off) = make_float2(1.0f / (1.0f + expf(-a0)),
                                                       1.0f / (1.0f + expf(-a1)));
                } else if (EPI == 4) {
                    *(float2*)(Cm + off) = make_float2(fmaxf(v0 + bv0, 0.0f),
                                                       fmaxf(v1 + bv1, 0.0f));
                } else if (EPI == 5) {
                    float2 old = *(float2*)(Cm + off);
                    float r0 = 1.0f / (1.0f + expf(-(old.x + v0 + bv0)));
                    float r1 = 1.0f / (1.0f + expf(-(old.y + v1 + bv1)));
                    float2 hv = *(const float2*)(Hp + off);
                    float m0v = r0 * hv.x, m1v = r1 * hv.y;
                    *(uint32_t*)(oh + off) = split_pack(m0v, m1v);
                    *(uint32_t*)(ol + off) = split_pack_lo(m0v, m1v);
                } else if (EPI == 6) {
                    float2 old = *(float2*)(Cm + off);
                    float t0 = tanhf(old.x + v0 + bv0);
                    float t1 = tanhf(old.y + v1 + bv1);
                    float2 zv = *(const float2*)(Zp + off);
                    float2 hv = *(const float2*)(Hp + off);
                    float pr = g_probs[pidx];
                    float2 ha = *(float2*)(Hacc + off);
                    ha.x += pr * (zv.x * hv.x + (1.0f - zv.x) * t0);
                    ha.y += pr * (zv.y * hv.y + (1.0f - zv.y) * t1);
                    *(float2*)(Hacc + off) = ha;
                }
            }
        }
    }
}

// ---------------- GCN propagation ----------------
// 512-wide: out[i] = bias + selfnorm*T[i] + sum norm*T[src]; emits split (+optional fp32)
template <bool WF32>
__global__ void __launch_bounds__(128) prop_split_kernel(
    const float* __restrict__ T, const float* __restrict__ bias,
    float* __restrict__ outf,
    __nv_bfloat16* __restrict__ oh, __nv_bfloat16* __restrict__ ol) {
    int i = blockIdx.x;
    int t = threadIdx.x;
    const float4* T4 = (const float4*)T;
    float4 b = ((const float4*)bias)[t];
    float sn = g_normself[i];
    float4 v = T4[(size_t)i * C4 + t];
    float4 acc = make_float4(b.x + sn * v.x, b.y + sn * v.y, b.z + sn * v.z, b.w + sn * v.w);
    int beg = g_rowptr[i];
    int end = g_rowptr[i + 1];
    for (int e = beg; e < end; e++) {
        int s = g_csrsrc[e];
        float w = g_csrnorm[e];
        float4 u = T4[(size_t)s * C4 + t];
        acc.x = fmaf(w, u.x, acc.x);
        acc.y = fmaf(w, u.y, acc.y);
        acc.z = fmaf(w, u.z, acc.z);
        acc.w = fmaf(w, u.w, acc.w);
    }
    if (WF32) ((float4*)outf)[(size_t)i * C4 + t] = acc;
    size_t off = (size_t)i * CC + t * 4;
    *(uint32_t*)(oh + off) = split_pack(acc.x, acc.y);
    *(uint32_t*)(oh + off + 2) = split_pack(acc.z, acc.w);
    *(uint32_t*)(ol + off) = split_pack_lo(acc.x, acc.y);
    *(uint32_t*)(ol + off + 2) = split_pack_lo(acc.z, acc.w);
}

// 128-wide: Xs = S*Xp (no bias), 4 nodes per block (one warp each)
__global__ void __launch_bounds__(128) prop128_kernel(
    const float* __restrict__ Xp,
    __nv_bfloat16* __restrict__ oh, __nv_bfloat16* __restrict__ ol) {
    int i = blockIdx.x * 4 + (threadIdx.x >> 5);
    int t = threadIdx.x & 31;
    if (i >= NN) return;
    const float4* X4 = (const float4*)Xp;
    float sn = g_normself[i];
    float4 v = X4[(size_t)i * F4 + t];
    float4 acc = make_float4(sn * v.x, sn * v.y, sn * v.z, sn * v.w);
    int beg = g_rowptr[i];
    int end = g_rowptr[i + 1];
    for (int e = beg; e < end; e++) {
        int s = g_csrsrc[e];
        float w = g_csrnorm[e];
        float4 u = X4[(size_t)s * F4 + t];
        acc.x = fmaf(w, u.x, acc.x);
        acc.y = fmaf(w, u.y, acc.y);
        acc.z = fmaf(w, u.z, acc.z);
        acc.w = fmaf(w, u.w, acc.w);
    }
    size_t off = (size_t)i * FF + t * 4;
    *(uint32_t*)(oh + off) = split_pack(acc.x, acc.y);
    *(uint32_t*)(oh + off + 2) = split_pack(acc.z, acc.w);
    *(uint32_t*)(ol + off) = split_pack_lo(acc.x, acc.y);
    *(uint32_t*)(ol + off + 2) = split_pack_lo(acc.z, acc.w);
}

// ---------------- elementwise kernels ----------------
__global__ void extract_kernel(const float* __restrict__ x, int p, float* __restrict__ Xp) {
    int idx = blockIdx.x * blockDim.x + threadIdx.x;
    if (idx < NN * FF) Xp[idx] = x[(size_t)idx * PP + p];
}

__global__ void zero_f_kernel(float* __restrict__ a, int n) {
    int idx = blockIdx.x * blockDim.x + threadIdx.x;
    if (idx < n) a[idx] = 0.0f;
}

__global__ void relu_split_kernel(const float* __restrict__ src,
                                  __nv_bfloat16* __restrict__ oh,
                                  __nv_bfloat16* __restrict__ ol) {
    int idx = blockIdx.x * blockDim.x + threadIdx.x;
    if (idx < NN * C4) {
        float4 v = ((const float4*)src)[idx];
        v.x = fmaxf(v.x, 0.f); v.y = fmaxf(v.y, 0.f);
        v.z = fmaxf(v.z, 0.f); v.w = fmaxf(v.w, 0.f);
        size_t off = (size_t)idx * 4;
        *(uint32_t*)(oh + off) = split_pack(v.x, v.y);
        *(uint32_t*)(oh + off + 2) = split_pack(v.z, v.w);
        *(uint32_t*)(ol + off) = split_pack_lo(v.x, v.y);
        *(uint32_t*)(ol + off + 2) = split_pack_lo(v.z, v.w);
    }
}

__global__ void lin2_kernel(const float* __restrict__ hid, const float* __restrict__ w,
                            const float* __restrict__ b, float* __restrict__ out) {
    int n = blockIdx.x * 8 + (threadIdx.x >> 5);
    int lane = threadIdx.x & 31;
    float s = 0.0f;
    for (int k = lane; k < HIDN; k += 32) s = fmaf(hid[(size_t)n * HIDN + k], w[k], s);
#pragma unroll
    for (int off = 16; off; off >>= 1) s += __shfl_down_sync(0xffffffffu, s, off);
    if (lane == 0) out[n] = s + b[0];
}

__global__ void copy_hidden_kernel(const float* __restrict__ Hacc, float* __restrict__ out) {
    int idx = blockIdx.x * blockDim.x + threadIdx.x;
    if (idx < NN * C4) {
        ((float4*)(out + NN))[idx] = ((const float4*)Hacc)[idx];
    }
}

// ---------------- host orchestration ----------------
#define GP(sym) ({ void* _p; cudaGetSymbolAddress(&_p, sym); (__nv_bfloat16*)_p; })
#define GPF(sym) ({ void* _p; cudaGetSymbolAddress(&_p, sym); (float*)_p; })

struct GemmArgs {
    const __nv_bfloat16 *Ah, *Al, *Bh, *Bl;
    float* Cm;
    const float* bias;
    const float* Zp;
    const float* Hp;
    float* Hacc;
    __nv_bfloat16 *oh, *ol;
    int pidx, M, N, K;
};

template <int EPI>
static inline void launch_gemm(const GemmArgs& a) {
    dim3 grid(a.N / BN, (a.M + BM - 1) / BM);
    bf3_gemm<EPI><<<grid, 256, SMEM_BYTES>>>(a.Ah, a.Al, a.Bh, a.Bl, a.Cm, a.bias,
                                             a.Zp, a.Hp, a.Hacc, a.oh, a.ol,
                                             a.pidx, a.M, a.N, a.K);
}

extern "C" void kernel_launch(void* const* d_in, const int* in_sizes, int n_in,
                              void* d_out, int out_size) {
    const float* x     = (const float*)d_in[0];
    const int*   ei    = (const int*)d_in[1];
    const float* ea    = (const float*)d_in[2];
    const float* W1    = (const float*)d_in[3];
    const float* b1    = (const float*)d_in[4];
    const float* W2    = (const float*)d_in[5];
    const float* b2    = (const float*)d_in[6];
    const float* W3    = (const float*)d_in[7];
    const float* b3    = (const float*)d_in[8];
    const float* W4    = (const float*)d_in[9];
    const float* b4    = (const float*)d_in[10];
    const float* W5    = (const float*)d_in[11];
    const float* b5    = (const float*)d_in[12];
    const float* Wz    = (const float*)d_in[13];
    const float* bz    = (const float*)d_in[14];
    const float* Lz_w  = (const float*)d_in[15];
    const float* Lz_b  = (const float*)d_in[16];
    const float* Wr    = (const float*)d_in[17];
    const float* br    = (const float*)d_in[18];
    const float* Lr_w  = (const float*)d_in[19];
    const float* Lr_b  = (const float*)d_in[20];
    const float* Wh    = (const float*)d_in[21];
    const float* bh    = (const float*)d_in[22];
    const float* Lh_w  = (const float*)d_in[23];
    const float* Lh_b  = (const float*)d_in[24];
    const float* attn  = (const float*)d_in[25];
    const float* lin1w = (const float*)d_in[26];
    const float* lin1b = (const float*)d_in[27];
    const float* lin2w = (const float*)d_in[28];
    const float* lin2b = (const float*)d_in[29];
    float* out = (float*)d_out;

    static bool attr_done = false;
    if (!attr_done) {
        cudaFuncSetAttribute(bf3_gemm<0>, cudaFuncAttributeMaxDynamicSharedMemorySize, SMEM_BYTES);
        cudaFuncSetAttribute(bf3_gemm<1>, cudaFuncAttributeMaxDynamicSharedMemorySize, SMEM_BYTES);
        cudaFuncSetAttribute(bf3_gemm<2>, cudaFuncAttributeMaxDynamicSharedMemorySize, SMEM_BYTES);
        cudaFuncSetAttribute(bf3_gemm<4>, cudaFuncAttributeMaxDynamicSharedMemorySize, SMEM_BYTES);
        cudaFuncSetAttribute(bf3_gemm<5>, cudaFuncAttributeMaxDynamicSharedMemorySize, SMEM_BYTES);
        cudaFuncSetAttribute(bf3_gemm<6>, cudaFuncAttributeMaxDynamicSharedMemorySize, SMEM_BYTES);
        attr_done = true;
    }

    float* pXp   = GPF(g_Xp);
    float* pT    = GPF(g_T);
    float* pH    = GPF(g_H);
    float* pZ    = GPF(g_Z);
    float* pHt   = GPF(g_Ht);
    float* pHacc = GPF(g_Hacc);
    float* phid1 = GPF(g_hid1);
    float* pMtmp = GPF(g_Mtmp);
    float* pbvz  = GPF(g_bvz);
    float* pbvr  = GPF(g_bvr);
    float* pbvh  = GPF(g_bvh);

    __nv_bfloat16 *pXsh = GP(g_Xsh), *pXsl = GP(g_Xsl);
    __nv_bfloat16 *pBAh = GP(g_BAh), *pBAl = GP(g_BAl);
    __nv_bfloat16 *pBBh = GP(g_BBh), *pBBl = GP(g_BBl);
    __nv_bfloat16 *pHh = GP(g_Hh), *pHl = GP(g_Hl);
    __nv_bfloat16 *pRmh = GP(g_Rmh), *pRml = GP(g_Rml);
    __nv_bfloat16 *pRAh = GP(g_RAh), *pRAl = GP(g_RAl);

    __nv_bfloat16 *pW1h = GP(g_W1h), *pW1l = GP(g_W1l);
    __nv_bfloat16 *pW2h = GP(g_W2h), *pW2l = GP(g_W2l);
    __nv_bfloat16 *pW3h = GP(g_W3h), *pW3l = GP(g_W3l);
    __nv_bfloat16 *pW4h = GP(g_W4h), *pW4l = GP(g_W4l);
    __nv_bfloat16 *pW5h = GP(g_W5h), *pW5l = GP(g_W5l);
    __nv_bfloat16 *pMzh = GP(g_Mzh), *pMzl = GP(g_Mzl);
    __nv_bfloat16 *pMrh = GP(g_Mrh), *pMrl = GP(g_Mrl);
    __nv_bfloat16 *pMhh = GP(g_Mhh), *pMhl = GP(g_Mhl);
    __nv_bfloat16 *pLz2h = GP(g_Lz2h), *pLz2l = GP(g_Lz2l);
    __nv_bfloat16 *pLr2h = GP(g_Lr2h), *pLr2l = GP(g_Lr2l);
    __nv_bfloat16 *pLh2h = GP(g_Lh2h), *pLh2l = GP(g_Lh2l);
    __nv_bfloat16 *pL1th = GP(g_L1th), *pL1tl = GP(g_L1tl);

    const int gE  = (EE + 255) / 256;
    const int gN  = (NN + 255) / 256;
    const int gNC = (NN * CC + 255) / 256;
    const int gNC4 = (NN * C4 + 255) / 256;
    const int gNF = (NN * FF + 255) / 256;
    const int gW512 = (CC * CC + 255) / 256;
    const int gW128 = (CC * FF + 255) / 256;
    const int gWL1 = (HIDN * CC + 255) / 256;

    // graph setup + CSR
    init_node_arrays<<<gN, 256>>>();
    deg_edges_kernel<<<gE, 256>>>(ei, ea);
    deg_finalize_kernel<<<gN, 256>>>();
    scan_kernel<<<1, 1024>>>();
    scatter_kernel<<<gE, 256>>>(ei, ea);
    softmax4_kernel<<<1, 32>>>(attn);
    zero_f_kernel<<<gNC, 256>>>(pHacc, NN * CC);

    // weight transpose + split
    wt_split_kernel<<<gW128, 256>>>(W1, 0, CC, FF, pW1h, pW1l);
    wt_split_kernel<<<gW512, 256>>>(W2, 0, CC, CC, pW2h, pW2l);
    wt_split_kernel<<<gW512, 256>>>(W3, 0, CC, CC, pW3h, pW3l);
    wt_split_kernel<<<gW512, 256>>>(W4, 0, CC, CC, pW4h, pW4l);
    wt_split_kernel<<<gW512, 256>>>(W5, 0, CC, CC, pW5h, pW5l);
    wt_split_kernel<<<gW512, 256>>>(Lz_w, CC, CC, CC, pLz2h, pLz2l);
    wt_split_kernel<<<gW512, 256>>>(Lr_w, CC, CC, CC, pLr2h, pLr2l);
    wt_split_kernel<<<gW512, 256>>>(Lh_w, CC, CC, CC, pLh2h, pLh2l);
    wt_split_kernel<<<gWL1, 256>>>(lin1w, 0, HIDN, CC, pL1th, pL1tl);

    // folded gate weights: M* = W* @ L*_w[0:512]  and folded biases
    gatefold_kernel<<<gW128, 256>>>(Wz, Lz_w, pMtmp);
    wt_split_kernel<<<gW128, 256>>>(pMtmp, 0, CC, FF, pMzh, pMzl);
    gatefold_kernel<<<gW128, 256>>>(Wr, Lr_w, pMtmp);
    wt_split_kernel<<<gW128, 256>>>(pMtmp, 0, CC, FF, pMrh, pMrl);
    gatefold_kernel<<<gW128, 256>>>(Wh, Lh_w, pMtmp);
    wt_split_kernel<<<gW128, 256>>>(pMtmp, 0, CC, FF, pMhh, pMhl);
    gate_bias_kernel<<<2, 256>>>(Lz_w, Lz_b, bz, pbvz);
    gate_bias_kernel<<<2, 256>>>(Lr_w, Lr_b, br, pbvr);
    gate_bias_kernel<<<2, 256>>>(Lh_w, Lh_b, bh, pbvh);

    for (int p = 0; p < PP; p++) {
        extract_kernel<<<gNF, 256>>>(x, p, pXp);
        prop128_kernel<<<(NN + 3) / 4, 128>>>(pXp, pXsh, pXsl);

        GemmArgs a{};
        // h1 = Xs@W1 + b1 (split out)
        a = {pXsh, pXsl, pW1h, pW1l, nullptr, b1, nullptr, nullptr, nullptr,
             pBAh, pBAl, 0, NN, CC, FF};
        launch_gemm<1>(a);
        // h2 = S(h1@W2)+b2
        a = {pBAh, pBAl, pW2h, pW2l, pT, nullptr, nullptr, nullptr, nullptr,
             nullptr, nullptr, 0, NN, CC, CC};
        launch_gemm<0>(a);
        prop_split_kernel<false><<<NN, 128>>>(pT, b2, nullptr, pBBh, pBBl);
        // h3
        a.Ah = pBBh; a.Al = pBBl; a.Bh = pW3h; a.Bl = pW3l;
        launch_gemm<0>(a);
        prop_split_kernel<false><<<NN, 128>>>(pT, b3, nullptr, pBAh, pBAl);
        // h4
        a.Ah = pBAh; a.Al = pBAl; a.Bh = pW4h; a.Bl = pW4l;
        launch_gemm<0>(a);
        prop_split_kernel<false><<<NN, 128>>>(pT, b4, nullptr, pBBh, pBBl);
        // H
        a.Ah = pBBh; a.Al = pBBl; a.Bh = pW5h; a.Bl = pW5l;
        launch_gemm<0>(a);
        prop_split_kernel<true><<<NN, 128>>>(pT, b5, pH, pHh, pHl);

        // Z = sigmoid(Xs@Mz + H@Lz2 + bvz)
        a = {pXsh, pXsl, pMzh, pMzl, pZ, nullptr, nullptr, nullptr, nullptr,
             nullptr, nullptr, 0, NN, CC, FF};
        launch_gemm<0>(a);
        a = {pHh, pHl, pLz2h, pLz2l, pZ, pbvz, nullptr, nullptr, nullptr,
             nullptr, nullptr, 0, NN, CC, CC};
        launch_gemm<2>(a);

        // Rm = H * sigmoid(Xs@Mr + H@Lr2 + bvr)
        a = {pXsh, pXsl, pMrh, pMrl, pT, nullptr, nullptr, nullptr, nullptr,
             nullptr, nullptr, 0, NN, CC, FF};
        launch_gemm<0>(a);
        a = {pHh, pHl, pLr2h, pLr2l, pT, pbvr, nullptr, pH, nullptr,
             pRmh, pRml, 0, NN, CC, CC};
        launch_gemm<5>(a);

        // Ht partial then gru accumulate
        a = {pXsh, pXsl, pMhh, pMhl, pHt, nullptr, nullptr, nullptr, nullptr,
             nullptr, nullptr, 0, NN, CC, FF};
        launch_gemm<0>(a);
        a = {pRmh, pRml, pLh2h, pLh2l, pHt, pbvh, pZ, pH, pHacc,
             nullptr, nullptr, p, NN, CC, CC};
        launch_gemm<6>(a);
    }

    // head
    relu_split_kernel<<<gNC4, 256>>>(pHacc, pRAh, pRAl);
    GemmArgs a = {pRAh, pRAl, pL1th, pL1tl, phid1, lin1b, nullptr, nullptr, nullptr,
                  nullptr, nullptr, 0, NN, HIDN, CC};
    launch_gemm<4>(a);
    lin2_kernel<<<(NN + 7) / 8, 256>>>(phid1, lin2w, lin2b, out);
    copy_hidden_kernel<<<gNC4, 256>>>(pHacc, out);
}

// round 6
// speedup vs baseline: 3.6830x; 1.1866x over previous
#include <cuda_runtime.h>
#include <cuda_bf16.h>
#include <stdint.h>
#include <math.h>

#define NN 10000
#define FF 128
#define PP 4
#define EE 160000
#define CC 512
#define HIDN 256
#define C4 (CC/4)
#define F4 (FF/4)
#define MB (NN*PP)          /* batched M = 40000 */

// ---------------- scratch (static device memory; no allocations) ----------------
__device__ float g_deg[NN];
__device__ float g_dinv[NN];
__device__ float g_normself[NN];
__device__ int   g_counts[NN];
__device__ int   g_rowptr[NN + 1];
__device__ int   g_cursor[NN];
__device__ int   g_csrsrc[EE];
__device__ float g_csrnorm[EE];
__device__ float g_probs[PP];

// fp32 buffers (batched across timesteps)
__device__ float g_Xp[MB * FF];
__device__ float g_T[MB * CC];
__device__ float g_H[MB * CC];
__device__ float g_Z[MB * CC];
__device__ float g_Ht[MB * CC];
__device__ float g_hid1[NN * HIDN];
__device__ float g_Mtmp[FF * CC];
__device__ float g_bvz[CC], g_bvr[CC], g_bvh[CC];

// bf16 hi/lo activation planes (GEMM A operands), batched
__device__ __nv_bfloat16 g_Xsh[MB * FF], g_Xsl[MB * FF];
__device__ __nv_bfloat16 g_BAh[MB * CC], g_BAl[MB * CC];
__device__ __nv_bfloat16 g_BBh[MB * CC], g_BBl[MB * CC];
__device__ __nv_bfloat16 g_Hh[MB * CC],  g_Hl[MB * CC];
__device__ __nv_bfloat16 g_Rmh[MB * CC], g_Rml[MB * CC];
__device__ __nv_bfloat16 g_RAh[NN * CC], g_RAl[NN * CC];

// transposed+split weights [N][K] bf16 hi/lo
__device__ __nv_bfloat16 g_W1h[CC * FF], g_W1l[CC * FF];
__device__ __nv_bfloat16 g_W2h[CC * CC], g_W2l[CC * CC];
__device__ __nv_bfloat16 g_W3h[CC * CC], g_W3l[CC * CC];
__device__ __nv_bfloat16 g_W4h[CC * CC], g_W4l[CC * CC];
__device__ __nv_bfloat16 g_W5h[CC * CC], g_W5l[CC * CC];
__device__ __nv_bfloat16 g_Mzh[CC * FF], g_Mzl[CC * FF];
__device__ __nv_bfloat16 g_Mrh[CC * FF], g_Mrl[CC * FF];
__device__ __nv_bfloat16 g_Mhh[CC * FF], g_Mhl[CC * FF];
__device__ __nv_bfloat16 g_Lz2h[CC * CC], g_Lz2l[CC * CC];
__device__ __nv_bfloat16 g_Lr2h[CC * CC], g_Lr2l[CC * CC];
__device__ __nv_bfloat16 g_Lh2h[CC * CC], g_Lh2l[CC * CC];
__device__ __nv_bfloat16 g_L1th[HIDN * CC], g_L1tl[HIDN * CC];

__device__ __forceinline__ void split_bf(float x, __nv_bfloat16& h, __nv_bfloat16& l) {
    h = __float2bfloat16(x);
    l = __float2bfloat16(x - __bfloat162float(h));
}
__device__ __forceinline__ uint32_t pack_bf2(__nv_bfloat16 a, __nv_bfloat16 b) {
    __nv_bfloat162 t(a, b);
    return *(uint32_t*)&t;
}
__device__ __forceinline__ uint32_t split_pack(float a, float b) {
    __nv_bfloat16 h0, l0, h1, l1;
    split_bf(a, h0, l0); split_bf(b, h1, l1);
    return pack_bf2(h0, h1);
}
__device__ __forceinline__ uint32_t split_pack_lo(float a, float b) {
    __nv_bfloat16 h0, l0, h1, l1;
    split_bf(a, h0, l0); split_bf(b, h1, l1);
    return pack_bf2(l0, l1);
}

// ---------------- graph setup kernels ----------------
__global__ void init_node_arrays() {
    int i = blockIdx.x * blockDim.x + threadIdx.x;
    if (i < NN) { g_deg[i] = 0.0f; g_counts[i] = 0; g_cursor[i] = 0; }
}

__global__ void deg_edges_kernel(const int* __restrict__ ei, const float* __restrict__ ea) {
    int e = blockIdx.x * blockDim.x + threadIdx.x;
    if (e < EE) {
        int dst = ei[EE + e];
        atomicAdd(&g_deg[dst], ea[e]);
        atomicAdd(&g_counts[dst], 1);
    }
}

__global__ void deg_finalize_kernel() {
    int i = blockIdx.x * blockDim.x + threadIdx.x;
    if (i < NN) {
        float d = g_deg[i] + 1.0f;
        float di = (d > 0.0f) ? rsqrtf(d) : 0.0f;
        g_dinv[i] = di;
        g_normself[i] = di * di;
    }
}

__global__ void scan_kernel() {
    __shared__ int part[1024];
    const int per = 10;
    int t = threadIdx.x;
    int base = t * per;
    int loc[per];
    int s = 0;
#pragma unroll
    for (int i = 0; i < per; i++) {
        int idx = base + i;
        int v = (idx < NN) ? g_counts[idx] : 0;
        loc[i] = s; s += v;
    }
    part[t] = s;
    __syncthreads();
    for (int off = 1; off < 1024; off <<= 1) {
        int v = (t >= off) ? part[t - off] : 0;
        __syncthreads();
        part[t] += v;
        __syncthreads();
    }
    int offb = (t == 0) ? 0 : part[t - 1];
#pragma unroll
    for (int i = 0; i < per; i++) {
        int idx = base + i;
        if (idx < NN) g_rowptr[idx] = offb + loc[i];
    }
    if (t == 1023) g_rowptr[NN] = part[1023];
}

__global__ void scatter_kernel(const int* __restrict__ ei, const float* __restrict__ ea) {
    int e = blockIdx.x * blockDim.x + threadIdx.x;
    if (e < EE) {
        int src = ei[e];
        int dst = ei[EE + e];
        float nv = g_dinv[src] * ea[e] * g_dinv[dst];
        int pos = atomicAdd(&g_cursor[dst], 1);
        int slot = g_rowptr[dst] + pos;
        g_csrsrc[slot] = src;
        g_csrnorm[slot] = nv;
    }
}

__global__ void softmax4_kernel(const float* __restrict__ attn) {
    if (threadIdx.x == 0 && blockIdx.x == 0) {
        float m = attn[0];
        for (int p = 1; p < PP; p++) m = fmaxf(m, attn[p]);
        float s = 0.0f, e[PP];
        for (int p = 0; p < PP; p++) { e[p] = expf(attn[p] - m); s += e[p]; }
        for (int p = 0; p < PP; p++) g_probs[p] = e[p] / s;
    }
}

__global__ void wt_split_kernel(const float* __restrict__ W, int k0, int N, int Kb,
                                __nv_bfloat16* __restrict__ oh, __nv_bfloat16* __restrict__ ol) {
    int idx = blockIdx.x * blockDim.x + threadIdx.x;
    if (idx < N * Kb) {
        int n = idx / Kb;
        int k = idx - n * Kb;
        float v = W[(size_t)(k0 + k) * N + n];
        __nv_bfloat16 h, l;
        split_bf(v, h, l);
        oh[idx] = h; ol[idx] = l;
    }
}

__global__ void gatefold_kernel(const float* __restrict__ Wsm, const float* __restrict__ Lw,
                                float* __restrict__ M) {
    int idx = blockIdx.x * blockDim.x + threadIdx.x;
    if (idx < FF * CC) {
        int f = idx / CC, n = idx - f * CC;
        float s = 0.0f;
        for (int k = 0; k < CC; k++)
            s = fmaf(Wsm[(size_t)f * CC + k], Lw[(size_t)k * CC + n], s);
        M[idx] = s;
    }
}

__global__ void gate_bias_kernel(const float* __restrict__ Lw, const float* __restrict__ Lb,
                                 const float* __restrict__ bsmall, float* __restrict__ bv) {
    int n = blockIdx.x * blockDim.x + threadIdx.x;
    if (n < CC) {
        float s = Lb[n];
        for (int k = 0; k < CC; k++)
            s = fmaf(bsmall[k], Lw[(size_t)k * CC + n], s);
        bv[n] = s;
    }
}

// ---------------- bf16x3 tensor-core GEMM (ldmatrix, pre-split operands) ----------------
#define BM 128
#define BN 64
#define BKC 32
#define TSTR 40
#define A_SZ (BM * TSTR)
#define B_SZ (BN * TSTR)
#define STG  (2 * A_SZ + 2 * B_SZ)
#define SMEM_BYTES (2 * STG * 2)

__device__ __forceinline__ void mma16816(float* c, const uint32_t* a, const uint32_t* b) {
    asm volatile(
        "mma.sync.aligned.m16n8k16.row.col.f32.bf16.bf16.f32 "
        "{%0,%1,%2,%3}, {%4,%5,%6,%7}, {%8,%9}, {%0,%1,%2,%3};"
        : "+f"(c[0]), "+f"(c[1]), "+f"(c[2]), "+f"(c[3])
        : "r"(a[0]), "r"(a[1]), "r"(a[2]), "r"(a[3]), "r"(b[0]), "r"(b[1]));
}

__device__ __forceinline__ void ldsm_x4(const void* p, uint32_t* r) {
    uint32_t addr = (uint32_t)__cvta_generic_to_shared(p);
    asm volatile("ldmatrix.sync.aligned.m8n8.x4.shared.b16 {%0,%1,%2,%3}, [%4];"
        : "=r"(r[0]), "=r"(r[1]), "=r"(r[2]), "=r"(r[3]) : "r"(addr));
}

// EPI: 0 store fp32; 1 split(acc+bias)->planes; 2 sigmoid(old+acc+bias)->fp32;
//      3 tanh(old+acc+bias)->fp32; 4 relu(acc+bias)->fp32;
//      5 sigmoid(old+acc+bias)*H->planes
template <int EPI>
__global__ void __launch_bounds__(256) bf3_gemm(
    const __nv_bfloat16* __restrict__ Ah, const __nv_bfloat16* __restrict__ Al,
    const __nv_bfloat16* __restrict__ Bh, const __nv_bfloat16* __restrict__ Bl,
    float* __restrict__ Cm, const float* __restrict__ bias,
    const float* __restrict__ Hp,
    __nv_bfloat16* __restrict__ oh, __nv_bfloat16* __restrict__ ol,
    int M, int N, int K) {
    extern __shared__ __align__(16) __nv_bfloat16 sm[];

    int tid = threadIdx.x;
    int m0 = blockIdx.y * BM;
    int n0 = blockIdx.x * BN;
    int warp = tid >> 5, lane = tid & 31;
    int wm = warp >> 1, wn = warp & 1;
    int g = lane >> 2, tg = lane & 3;

    float c[2][4][4];
#pragma unroll
    for (int mt = 0; mt < 2; mt++)
#pragma unroll
        for (int nt = 0; nt < 4; nt++)
#pragma unroll
            for (int i = 0; i < 4; i++) c[mt][nt][i] = 0.0f;

    int a_r0 = tid >> 2, a_q0 = tid & 3;
    int a_r1 = (tid + 256) >> 2, a_q1 = (tid + 256) & 3;
    int b_n = tid >> 2, b_q = tid & 3;

    uint4 rAh[2], rAl[2], rBh, rBl;
    const uint4 z4 = make_uint4(0u, 0u, 0u, 0u);

    auto load_glb = [&](int k0) {
        int m = m0 + a_r0;
        size_t off = (size_t)m * K + k0 + a_q0 * 8;
        rAh[0] = (m < M) ? *(const uint4*)(Ah + off) : z4;
        rAl[0] = (m < M) ? *(const uint4*)(Al + off) : z4;
        m = m0 + a_r1;
        off = (size_t)m * K + k0 + a_q1 * 8;
        rAh[1] = (m < M) ? *(const uint4*)(Ah + off) : z4;
        rAl[1] = (m < M) ? *(const uint4*)(Al + off) : z4;
        size_t boff = (size_t)(n0 + b_n) * K + k0 + b_q * 8;
        rBh = *(const uint4*)(Bh + boff);
        rBl = *(const uint4*)(Bl + boff);
    };

    auto store_smem = [&](int st) {
        __nv_bfloat16* Ahs = sm + st * STG;
        __nv_bfloat16* Als = Ahs + A_SZ;
        __nv_bfloat16* Bhs = Als + A_SZ;
        __nv_bfloat16* Bls = Bhs + B_SZ;
        *(uint4*)(Ahs + a_r0 * TSTR + a_q0 * 8) = rAh[0];
        *(uint4*)(Ahs + a_r1 * TSTR + a_q1 * 8) = rAh[1];
        *(uint4*)(Als + a_r0 * TSTR + a_q0 * 8) = rAl[0];
        *(uint4*)(Als + a_r1 * TSTR + a_q1 * 8) = rAl[1];
        *(uint4*)(Bhs + b_n * TSTR + b_q * 8) = rBh;
        *(uint4*)(Bls + b_n * TSTR + b_q * 8) = rBl;
    };

    auto compute = [&](int st) {
        const __nv_bfloat16* Ahs = sm + st * STG;
        const __nv_bfloat16* Als = Ahs + A_SZ;
        const __nv_bfloat16* Bhs = Als + A_SZ;
        const __nv_bfloat16* Bls = Bhs + B_SZ;
#pragma unroll
        for (int ks = 0; ks < 2; ks++) {
            uint32_t af[2][2][4];
            int arow = (lane & 15);
            int acol = ks * 16 + (lane >> 4) * 8;
#pragma unroll
            for (int mt = 0; mt < 2; mt++) {
                int r = wm * 32 + mt * 16 + arow;
                ldsm_x4(Ahs + r * TSTR + acol, af[mt][0]);
                ldsm_x4(Als + r * TSTR + acol, af[mt][1]);
            }
            uint32_t bfr[4][2][2];
            int bm_ = lane >> 3;
            int brow_in = lane & 7;
            int bro = (bm_ >> 1) * 8 + brow_in;
            int bco = ks * 16 + (bm_ & 1) * 8;
#pragma unroll
            for (int ntp = 0; ntp < 2; ntp++) {
                int nr = wn * 32 + ntp * 16 + bro;
                uint32_t t4[4];
                ldsm_x4(Bhs + nr * TSTR + bco, t4);
                bfr[ntp * 2][0][0] = t4[0]; bfr[ntp * 2][0][1] = t4[1];
                bfr[ntp * 2 + 1][0][0] = t4[2]; bfr[ntp * 2 + 1][0][1] = t4[3];
                ldsm_x4(Bls + nr * TSTR + bco, t4);
                bfr[ntp * 2][1][0] = t4[0]; bfr[ntp * 2][1][1] = t4[1];
                bfr[ntp * 2 + 1][1][0] = t4[2]; bfr[ntp * 2 + 1][1][1] = t4[3];
            }
#pragma unroll
            for (int mt = 0; mt < 2; mt++)
#pragma unroll
                for (int nt = 0; nt < 4; nt++) {
                    mma16816(c[mt][nt], af[mt][0], bfr[nt][0]);
                    mma16816(c[mt][nt], af[mt][1], bfr[nt][0]);
                    mma16816(c[mt][nt], af[mt][0], bfr[nt][1]);
                }
        }
    };

    int nchunks = K / BKC;
    load_glb(0);
    store_smem(0);
    __syncthreads();
    for (int ch = 0; ch < nchunks; ch++) {
        int st = ch & 1;
        if (ch + 1 < nchunks) load_glb((ch + 1) * BKC);
        compute(st);
        if (ch + 1 < nchunks) store_smem(st ^ 1);
        __syncthreads();
    }

#pragma unroll
    for (int mt = 0; mt < 2; mt++) {
#pragma unroll
        for (int nt = 0; nt < 4; nt++) {
            int col = n0 + wn * 32 + nt * 8 + tg * 2;
            float bv0 = 0.f, bv1 = 0.f;
            if (EPI != 0) { bv0 = __ldg(&bias[col]); bv1 = __ldg(&bias[col + 1]); }
#pragma unroll
            for (int half = 0; half < 2; half++) {
                int row = m0 + wm * 32 + mt * 16 + g + half * 8;
                if (row >= M) continue;
                float v0 = c[mt][nt][half * 2 + 0];
                float v1 = c[mt][nt][half * 2 + 1];
                size_t off = (size_t)row * N + col;
                if (EPI == 0) {
                    *(float2*)(Cm + off) = make_float2(v0, v1);
                } else if (EPI == 1) {
                    float a0 = v0 + bv0, a1 = v1 + bv1;
                    *(uint32_t*)(oh + off) = split_pack(a0, a1);
                    *(uint32_t*)(ol + off) = split_pack_lo(a0, a1);
                } else if (EPI == 2) {
                    float2 old = *(float2*)(Cm + off);
                    float a0 = old.x + v0 + bv0, a1 = old.y + v1 + bv1;
                    *(float2*)(Cm + off) = make_float2(1.0f / (1.0f + expf(-a0)),
                                                       1.0f / (1.0f + expf(-a1)));
                } else if (EPI == 3) {
                    float2 old = *(float2*)(Cm + off);
                    *(float2*)(Cm + off) = make_float2(tanhf(old.x + v0 + bv0),
                                                       tanhf(old.y + v1 + bv1));
                } else if (EPI == 4) {
                    *(float2*)(Cm + off) = make_float2(fmaxf(v0 + bv0, 0.0f),
                                                       fmaxf(v1 + bv1, 0.0f));
                } else if (EPI == 5) {
                    float2 old = *(float2*)(Cm + off);
                    float r0 = 1.0f / (1.0f + expf(-(old.x + v0 + bv0)));
                    float r1 = 1.0f / (1.0f + expf(-(old.y + v1 + bv1)));
                    float2 hv = *(const float2*)(Hp + off);
                    float m0v = r0 * hv.x, m1v = r1 * hv.y;
                    *(uint32_t*)(oh + off) = split_pack(m0v, m1v);
                    *(uint32_t*)(ol + off) = split_pack_lo(m0v, m1v);
                }
            }
        }
    }
}

// ---------------- batched GCN propagation ----------------
// rows r = p*NN + i over all 4 timesteps
template <bool WF32>
__global__ void __launch_bounds__(128) prop_split_kernel(
    const float* __restrict__ T, const float* __restrict__ bias,
    float* __restrict__ outf,
    __nv_bfloat16* __restrict__ oh, __nv_bfloat16* __restrict__ ol) {
    int r = blockIdx.x;
    int p = r / NN;
    int i = r - p * NN;
    int t = threadIdx.x;
    const float4* T4 = (const float4*)T;
    float4 b = ((const float4*)bias)[t];
    float sn = g_normself[i];
    float4 v = T4[(size_t)r * C4 + t];
    float4 acc = make_float4(b.x + sn * v.x, b.y + sn * v.y, b.z + sn * v.z, b.w + sn * v.w);
    int beg = g_rowptr[i];
    int end = g_rowptr[i + 1];
    int base = p * NN;
    for (int e = beg; e < end; e++) {
        int s = g_csrsrc[e];
        float w = g_csrnorm[e];
        float4 u = T4[(size_t)(base + s) * C4 + t];
        acc.x = fmaf(w, u.x, acc.x);
        acc.y = fmaf(w, u.y, acc.y);
        acc.z = fmaf(w, u.z, acc.z);
        acc.w = fmaf(w, u.w, acc.w);
    }
    if (WF32) ((float4*)outf)[(size_t)r * C4 + t] = acc;
    size_t off = (size_t)r * CC + t * 4;
    *(uint32_t*)(oh + off) = split_pack(acc.x, acc.y);
    *(uint32_t*)(oh + off + 2) = split_pack(acc.z, acc.w);
    *(uint32_t*)(ol + off) = split_pack_lo(acc.x, acc.y);
    *(uint32_t*)(ol + off + 2) = split_pack_lo(acc.z, acc.w);
}

// 128-wide batched: Xs = S*Xp, 4 rows per block (one warp each)
__global__ void __launch_bounds__(128) prop128_kernel(
    const float* __restrict__ Xp,
    __nv_bfloat16* __restrict__ oh, __nv_bfloat16* __restrict__ ol) {
    int r = blockIdx.x * 4 + (threadIdx.x >> 5);
    int t = threadIdx.x & 31;
    if (r >= MB) return;
    int p = r / NN;
    int i = r - p * NN;
    const float4* X4 = (const float4*)Xp;
    float sn = g_normself[i];
    float4 v = X4[(size_t)r * F4 + t];
    float4 acc = make_float4(sn * v.x, sn * v.y, sn * v.z, sn * v.w);
    int beg = g_rowptr[i];
    int end = g_rowptr[i + 1];
    int base = p * NN;
    for (int e = beg; e < end; e++) {
        int s = g_csrsrc[e];
        float w = g_csrnorm[e];
        float4 u = X4[(size_t)(base + s) * F4 + t];
        acc.x = fmaf(w, u.x, acc.x);
        acc.y = fmaf(w, u.y, acc.y);
        acc.z = fmaf(w, u.z, acc.z);
        acc.w = fmaf(w, u.w, acc.w);
    }
    size_t off = (size_t)r * FF + t * 4;
    *(uint32_t*)(oh + off) = split_pack(acc.x, acc.y);
    *(uint32_t*)(oh + off + 2) = split_pack(acc.z, acc.w);
    *(uint32_t*)(ol + off) = split_pack_lo(acc.x, acc.y);
    *(uint32_t*)(ol + off + 2) = split_pack_lo(acc.z, acc.w);
}

// ---------------- elementwise kernels ----------------
// extract all 4 timesteps at once: Xp[p*NN*FF + idx] = x[idx*PP + p]
__global__ void extract_all_kernel(const float* __restrict__ x, float* __restrict__ Xp) {
    int idx = blockIdx.x * blockDim.x + threadIdx.x;
    if (idx < NN * FF) {
        float4 v = ((const float4*)x)[idx];
        Xp[idx] = v.x;
        Xp[NN * FF + idx] = v.y;
        Xp[2 * NN * FF + idx] = v.z;
        Xp[3 * NN * FF + idx] = v.w;
    }
}

// fused: Hacc = sum_p probs[p]*(Z*H+(1-Z)*Ht); write out_hidden; relu-split planes
__global__ void gru_reduce_kernel(const float* __restrict__ Z, const float* __restrict__ H,
                                  const float* __restrict__ Ht, float* __restrict__ out,
                                  __nv_bfloat16* __restrict__ oh, __nv_bfloat16* __restrict__ ol) {
    int idx = blockIdx.x * blockDim.x + threadIdx.x;  // float4 index over NN*C4
    if (idx >= NN * C4) return;
    int i = idx >> 7;           // C4 = 128
    int t = idx & 127;
    float4 acc = make_float4(0.f, 0.f, 0.f, 0.f);
#pragma unroll
    for (int p = 0; p < PP; p++) {
        size_t o4 = (size_t)(p * NN + i) * C4 + t;
        float4 z = ((const float4*)Z)[o4];
        float4 h = ((const float4*)H)[o4];
        float4 ht = ((const float4*)Ht)[o4];
        float pr = g_probs[p];
        acc.x += pr * (z.x * h.x + (1.0f - z.x) * ht.x);
        acc.y += pr * (z.y * h.y + (1.0f - z.y) * ht.y);
        acc.z += pr * (z.z * h.z + (1.0f - z.z) * ht.z);
        acc.w += pr * (z.w * h.w + (1.0f - z.w) * ht.w);
    }
    ((float4*)(out + NN))[idx] = acc;   // out_hidden
    float4 v = make_float4(fmaxf(acc.x, 0.f), fmaxf(acc.y, 0.f),
                           fmaxf(acc.z, 0.f), fmaxf(acc.w, 0.f));
    size_t off = (size_t)idx * 4;
    *(uint32_t*)(oh + off) = split_pack(v.x, v.y);
    *(uint32_t*)(oh + off + 2) = split_pack(v.z, v.w);
    *(uint32_t*)(ol + off) = split_pack_lo(v.x, v.y);
    *(uint32_t*)(ol + off + 2) = split_pack_lo(v.z, v.w);
}

__global__ void lin2_kernel(const float* __restrict__ hid, const float* __restrict__ w,
                            const float* __restrict__ b, float* __restrict__ out) {
    int n = blockIdx.x * 8 + (threadIdx.x >> 5);
    int lane = threadIdx.x & 31;
    float s = 0.0f;
    for (int k = lane; k < HIDN; k += 32) s = fmaf(hid[(size_t)n * HIDN + k], w[k], s);
#pragma unroll
    for (int off = 16; off; off >>= 1) s += __shfl_down_sync(0xffffffffu, s, off);
    if (lane == 0) out[n] = s + b[0];
}

// ---------------- host orchestration ----------------
#define GP(sym) ({ void* _p; cudaGetSymbolAddress(&_p, sym); (__nv_bfloat16*)_p; })
#define GPF(sym) ({ void* _p; cudaGetSymbolAddress(&_p, sym); (float*)_p; })

struct GemmArgs {
    const __nv_bfloat16 *Ah, *Al, *Bh, *Bl;
    float* Cm;
    const float* bias;
    const float* Hp;
    __nv_bfloat16 *oh, *ol;
    int M, N, K;
};

template <int EPI>
static inline void launch_gemm(const GemmArgs& a) {
    dim3 grid(a.N / BN, (a.M + BM - 1) / BM);
    bf3_gemm<EPI><<<grid, 256, SMEM_BYTES>>>(a.Ah, a.Al, a.Bh, a.Bl, a.Cm, a.bias,
                                             a.Hp, a.oh, a.ol, a.M, a.N, a.K);
}

extern "C" void kernel_launch(void* const* d_in, const int* in_sizes, int n_in,
                              void* d_out, int out_size) {
    const float* x     = (const float*)d_in[0];
    const int*   ei    = (const int*)d_in[1];
    const float* ea    = (const float*)d_in[2];
    const float* W1    = (const float*)d_in[3];
    const float* b1    = (const float*)d_in[4];
    const float* W2    = (const float*)d_in[5];
    const float* b2    = (const float*)d_in[6];
    const float* W3    = (const float*)d_in[7];
    const float* b3    = (const float*)d_in[8];
    const float* W4    = (const float*)d_in[9];
    const float* b4    = (const float*)d_in[10];
    const float* W5    = (const float*)d_in[11];
    const float* b5    = (const float*)d_in[12];
    const float* Wz    = (const float*)d_in[13];
    const float* bz    = (const float*)d_in[14];
    const float* Lz_w  = (const float*)d_in[15];
    const float* Lz_b  = (const float*)d_in[16];
    const float* Wr    = (const float*)d_in[17];
    const float* br    = (const float*)d_in[18];
    const float* Lr_w  = (const float*)d_in[19];
    const float* Lr_b  = (const float*)d_in[20];
    const float* Wh    = (const float*)d_in[21];
    const float* bh    = (const float*)d_in[22];
    const float* Lh_w  = (const float*)d_in[23];
    const float* Lh_b  = (const float*)d_in[24];
    const float* attn  = (const float*)d_in[25];
    const float* lin1w = (const float*)d_in[26];
    const float* lin1b = (const float*)d_in[27];
    const float* lin2w = (const float*)d_in[28];
    const float* lin2b = (const float*)d_in[29];
    float* out = (float*)d_out;

    static bool attr_done = false;
    if (!attr_done) {
        cudaFuncSetAttribute(bf3_gemm<0>, cudaFuncAttributeMaxDynamicSharedMemorySize, SMEM_BYTES);
        cudaFuncSetAttribute(bf3_gemm<1>, cudaFuncAttributeMaxDynamicSharedMemorySize, SMEM_BYTES);
        cudaFuncSetAttribute(bf3_gemm<2>, cudaFuncAttributeMaxDynamicSharedMemorySize, SMEM_BYTES);
        cudaFuncSetAttribute(bf3_gemm<3>, cudaFuncAttributeMaxDynamicSharedMemorySize, SMEM_BYTES);
        cudaFuncSetAttribute(bf3_gemm<4>, cudaFuncAttributeMaxDynamicSharedMemorySize, SMEM_BYTES);
        cudaFuncSetAttribute(bf3_gemm<5>, cudaFuncAttributeMaxDynamicSharedMemorySize, SMEM_BYTES);
        attr_done = true;
    }

    float* pXp   = GPF(g_Xp);
    float* pT    = GPF(g_T);
    float* pH    = GPF(g_H);
    float* pZ    = GPF(g_Z);
    float* pHt   = GPF(g_Ht);
    float* phid1 = GPF(g_hid1);
    float* pMtmp = GPF(g_Mtmp);
    float* pbvz  = GPF(g_bvz);
    float* pbvr  = GPF(g_bvr);
    float* pbvh  = GPF(g_bvh);

    __nv_bfloat16 *pXsh = GP(g_Xsh), *pXsl = GP(g_Xsl);
    __nv_bfloat16 *pBAh = GP(g_BAh), *pBAl = GP(g_BAl);
    __nv_bfloat16 *pBBh = GP(g_BBh), *pBBl = GP(g_BBl);
    __nv_bfloat16 *pHh = GP(g_Hh), *pHl = GP(g_Hl);
    __nv_bfloat16 *pRmh = GP(g_Rmh), *pRml = GP(g_Rml);
    __nv_bfloat16 *pRAh = GP(g_RAh), *pRAl = GP(g_RAl);

    __nv_bfloat16 *pW1h = GP(g_W1h), *pW1l = GP(g_W1l);
    __nv_bfloat16 *pW2h = GP(g_W2h), *pW2l = GP(g_W2l);
    __nv_bfloat16 *pW3h = GP(g_W3h), *pW3l = GP(g_W3l);
    __nv_bfloat16 *pW4h = GP(g_W4h), *pW4l = GP(g_W4l);
    __nv_bfloat16 *pW5h = GP(g_W5h), *pW5l = GP(g_W5l);
    __nv_bfloat16 *pMzh = GP(g_Mzh), *pMzl = GP(g_Mzl);
    __nv_bfloat16 *pMrh = GP(g_Mrh), *pMrl = GP(g_Mrl);
    __nv_bfloat16 *pMhh = GP(g_Mhh), *pMhl = GP(g_Mhl);
    __nv_bfloat16 *pLz2h = GP(g_Lz2h), *pLz2l = GP(g_Lz2l);
    __nv_bfloat16 *pLr2h = GP(g_Lr2h), *pLr2l = GP(g_Lr2l);
    __nv_bfloat16 *pLh2h = GP(g_Lh2h), *pLh2l = GP(g_Lh2l);
    __nv_bfloat16 *pL1th = GP(g_L1th), *pL1tl = GP(g_L1tl);

    const int gE  = (EE + 255) / 256;
    const int gN  = (NN + 255) / 256;
    const int gNC4 = (NN * C4 + 255) / 256;
    const int gNF = (NN * FF + 255) / 256;
    const int gW512 = (CC * CC + 255) / 256;
    const int gW128 = (CC * FF + 255) / 256;
    const int gWL1 = (HIDN * CC + 255) / 256;

    // graph setup + CSR
    init_node_arrays<<<gN, 256>>>();
    deg_edges_kernel<<<gE, 256>>>(ei, ea);
    deg_finalize_kernel<<<gN, 256>>>();
    scan_kernel<<<1, 1024>>>();
    scatter_kernel<<<gE, 256>>>(ei, ea);
    softmax4_kernel<<<1, 32>>>(attn);

    // weight transpose + split
    wt_split_kernel<<<gW128, 256>>>(W1, 0, CC, FF, pW1h, pW1l);
    wt_split_kernel<<<gW512, 256>>>(W2, 0, CC, CC, pW2h, pW2l);
    wt_split_kernel<<<gW512, 256>>>(W3, 0, CC, CC, pW3h, pW3l);
    wt_split_kernel<<<gW512, 256>>>(W4, 0, CC, CC, pW4h, pW4l);
    wt_split_kernel<<<gW512, 256>>>(W5, 0, CC, CC, pW5h, pW5l);
    wt_split_kernel<<<gW512, 256>>>(Lz_w, CC, CC, CC, pLz2h, pLz2l);
    wt_split_kernel<<<gW512, 256>>>(Lr_w, CC, CC, CC, pLr2h, pLr2l);
    wt_split_kernel<<<gW512, 256>>>(Lh_w, CC, CC, CC, pLh2h, pLh2l);
    wt_split_kernel<<<gWL1, 256>>>(lin1w, 0, HIDN, CC, pL1th, pL1tl);

    gatefold_kernel<<<gW128, 256>>>(Wz, Lz_w, pMtmp);
    wt_split_kernel<<<gW128, 256>>>(pMtmp, 0, CC, FF, pMzh, pMzl);
    gatefold_kernel<<<gW128, 256>>>(Wr, Lr_w, pMtmp);
    wt_split_kernel<<<gW128, 256>>>(pMtmp, 0, CC, FF, pMrh, pMrl);
    gatefold_kernel<<<gW128, 256>>>(Wh, Lh_w, pMtmp);
    wt_split_kernel<<<gW128, 256>>>(pMtmp, 0, CC, FF, pMhh, pMhl);
    gate_bias_kernel<<<2, 256>>>(Lz_w, Lz_b, bz, pbvz);
    gate_bias_kernel<<<2, 256>>>(Lr_w, Lr_b, br, pbvr);
    gate_bias_kernel<<<2, 256>>>(Lh_w, Lh_b, bh, pbvh);

    // ---- batched across all 4 timesteps (M = 40000) ----
    extract_all_kernel<<<gNF, 256>>>(x, pXp);
    prop128_kernel<<<(MB + 3) / 4, 128>>>(pXp, pXsh, pXsl);

    GemmArgs a{};
    // h1 = Xs@W1 + b1 (split out)
    a = {pXsh, pXsl, pW1h, pW1l, nullptr, b1, nullptr, pBAh, pBAl, MB, CC, FF};
    launch_gemm<1>(a);
    // layers 2..5
    a = {pBAh, pBAl, pW2h, pW2l, pT, nullptr, nullptr, nullptr, nullptr, MB, CC, CC};
    launch_gemm<0>(a);
    prop_split_kernel<false><<<MB, 128>>>(pT, b2, nullptr, pBBh, pBBl);
    a.Ah = pBBh; a.Al = pBBl; a.Bh = pW3h; a.Bl = pW3l;
    launch_gemm<0>(a);
    prop_split_kernel<false><<<MB, 128>>>(pT, b3, nullptr, pBAh, pBAl);
    a.Ah = pBAh; a.Al = pBAl; a.Bh = pW4h; a.Bl = pW4l;
    launch_gemm<0>(a);
    prop_split_kernel<false><<<MB, 128>>>(pT, b4, nullptr, pBBh, pBBl);
    a.Ah = pBBh; a.Al = pBBl; a.Bh = pW5h; a.Bl = pW5l;
    launch_gemm<0>(a);
    prop_split_kernel<true><<<MB, 128>>>(pT, b5, pH, pHh, pHl);

    // Z = sigmoid(Xs@Mz + H@Lz2 + bvz)
    a = {pXsh, pXsl, pMzh, pMzl, pZ, nullptr, nullptr, nullptr, nullptr, MB, CC, FF};
    launch_gemm<0>(a);
    a = {pHh, pHl, pLz2h, pLz2l, pZ, pbvz, nullptr, nullptr, nullptr, MB, CC, CC};
    launch_gemm<2>(a);

    // Rm = H * sigmoid(Xs@Mr + H@Lr2 + bvr)
    a = {pXsh, pXsl, pMrh, pMrl, pT, nullptr, nullptr, nullptr, nullptr, MB, CC, FF};
    launch_gemm<0>(a);
    a = {pHh, pHl, pLr2h, pLr2l, pT, pbvr, pH, pRmh, pRml, MB, CC, CC};
    launch_gemm<5>(a);

    // Ht = tanh(Xs@Mh + Rm@Lh2 + bvh)
    a = {pXsh, pXsl, pMhh, pMhl, pHt, nullptr, nullptr, nullptr, nullptr, MB, CC, FF};
    launch_gemm<0>(a);
    a = {pRmh, pRml, pLh2h, pLh2l, pHt, pbvh, nullptr, nullptr, nullptr, MB, CC, CC};
    launch_gemm<3>(a);

    // GRU combine over p + out_hidden + relu-split for head
    gru_reduce_kernel<<<gNC4, 256>>>(pZ, pH, pHt, out, pRAh, pRAl);

    // head
    a = {pRAh, pRAl, pL1th, pL1tl, phid1, lin1b, nullptr, nullptr, nullptr, NN, HIDN, CC};
    launch_gemm<4>(a);
    lin2_kernel<<<(NN + 7) / 8, 256>>>(phid1, lin2w, lin2b, out);
}

// round 7
// speedup vs baseline: 4.2627x; 1.1574x over previous
#include <cuda_runtime.h>
#include <cuda_bf16.h>
#include <stdint.h>
#include <math.h>

#define NN 10000
#define FF 128
#define PP 4
#define EE 160000
#define CC 512
#define HIDN 256
#define C4 (CC/4)
#define F4 (FF/4)
#define MB (NN*PP)

// ---------------- scratch (static device memory; no allocations) ----------------
__device__ float g_deg[NN];
__device__ float g_dinv[NN];
__device__ float g_normself[NN];
__device__ int   g_counts[NN];
__device__ int   g_rowptr[NN + 1];
__device__ int   g_cursor[NN];
__device__ int   g_csrsrc[EE];
__device__ float g_csrnorm[EE];
__device__ float g_probs[PP];

__device__ float g_Xp[MB * FF];
__device__ float g_T[MB * CC];
__device__ float g_H[MB * CC];
__device__ float g_Z[MB * CC];
__device__ float g_Ht[MB * CC];
__device__ float g_hid1[NN * HIDN];
__device__ float g_Mtmp[FF * CC];
__device__ float g_bvz[CC], g_bvr[CC], g_bvh[CC];

__device__ __nv_bfloat16 g_Xsh[MB * FF], g_Xsl[MB * FF];
__device__ __nv_bfloat16 g_BAh[MB * CC], g_BAl[MB * CC];
__device__ __nv_bfloat16 g_BBh[MB * CC], g_BBl[MB * CC];
__device__ __nv_bfloat16 g_Hh[MB * CC],  g_Hl[MB * CC];
__device__ __nv_bfloat16 g_Rmh[MB * CC], g_Rml[MB * CC];
__device__ __nv_bfloat16 g_RAh[NN * CC], g_RAl[NN * CC];

__device__ __nv_bfloat16 g_W1h[CC * FF], g_W1l[CC * FF];
__device__ __nv_bfloat16 g_W2h[CC * CC], g_W2l[CC * CC];
__device__ __nv_bfloat16 g_W3h[CC * CC], g_W3l[CC * CC];
__device__ __nv_bfloat16 g_W4h[CC * CC], g_W4l[CC * CC];
__device__ __nv_bfloat16 g_W5h[CC * CC], g_W5l[CC * CC];
__device__ __nv_bfloat16 g_Mzh[CC * FF], g_Mzl[CC * FF];
__device__ __nv_bfloat16 g_Mrh[CC * FF], g_Mrl[CC * FF];
__device__ __nv_bfloat16 g_Mhh[CC * FF], g_Mhl[CC * FF];
__device__ __nv_bfloat16 g_Lz2h[CC * CC], g_Lz2l[CC * CC];
__device__ __nv_bfloat16 g_Lr2h[CC * CC], g_Lr2l[CC * CC];
__device__ __nv_bfloat16 g_Lh2h[CC * CC], g_Lh2l[CC * CC];
__device__ __nv_bfloat16 g_L1th[HIDN * CC], g_L1tl[HIDN * CC];

__device__ __forceinline__ void split_bf(float x, __nv_bfloat16& h, __nv_bfloat16& l) {
    h = __float2bfloat16(x);
    l = __float2bfloat16(x - __bfloat162float(h));
}
__device__ __forceinline__ uint32_t pack_bf2(__nv_bfloat16 a, __nv_bfloat16 b) {
    __nv_bfloat162 t(a, b);
    return *(uint32_t*)&t;
}
__device__ __forceinline__ uint32_t split_pack(float a, float b) {
    __nv_bfloat16 h0, l0, h1, l1;
    split_bf(a, h0, l0); split_bf(b, h1, l1);
    return pack_bf2(h0, h1);
}
__device__ __forceinline__ uint32_t split_pack_lo(float a, float b) {
    __nv_bfloat16 h0, l0, h1, l1;
    split_bf(a, h0, l0); split_bf(b, h1, l1);
    return pack_bf2(l0, l1);
}

// ---------------- graph setup kernels ----------------
__global__ void init_node_arrays() {
    int i = blockIdx.x * blockDim.x + threadIdx.x;
    if (i < NN) { g_deg[i] = 0.0f; g_counts[i] = 0; g_cursor[i] = 0; }
}

__global__ void deg_edges_kernel(const int* __restrict__ ei, const float* __restrict__ ea) {
    int e = blockIdx.x * blockDim.x + threadIdx.x;
    if (e < EE) {
        int dst = ei[EE + e];
        atomicAdd(&g_deg[dst], ea[e]);
        atomicAdd(&g_counts[dst], 1);
    }
}

__global__ void deg_finalize_kernel() {
    int i = blockIdx.x * blockDim.x + threadIdx.x;
    if (i < NN) {
        float d = g_deg[i] + 1.0f;
        float di = (d > 0.0f) ? rsqrtf(d) : 0.0f;
        g_dinv[i] = di;
        g_normself[i] = di * di;
    }
}

__global__ void scan_kernel() {
    __shared__ int part[1024];
    const int per = 10;
    int t = threadIdx.x;
    int base = t * per;
    int loc[per];
    int s = 0;
#pragma unroll
    for (int i = 0; i < per; i++) {
        int idx = base + i;
        int v = (idx < NN) ? g_counts[idx] : 0;
        loc[i] = s; s += v;
    }
    part[t] = s;
    __syncthreads();
    for (int off = 1; off < 1024; off <<= 1) {
        int v = (t >= off) ? part[t - off] : 0;
        __syncthreads();
        part[t] += v;
        __syncthreads();
    }
    int offb = (t == 0) ? 0 : part[t - 1];
#pragma unroll
    for (int i = 0; i < per; i++) {
        int idx = base + i;
        if (idx < NN) g_rowptr[idx] = offb + loc[i];
    }
    if (t == 1023) g_rowptr[NN] = part[1023];
}

__global__ void scatter_kernel(const int* __restrict__ ei, const float* __restrict__ ea) {
    int e = blockIdx.x * blockDim.x + threadIdx.x;
    if (e < EE) {
        int src = ei[e];
        int dst = ei[EE + e];
        float nv = g_dinv[src] * ea[e] * g_dinv[dst];
        int pos = atomicAdd(&g_cursor[dst], 1);
        int slot = g_rowptr[dst] + pos;
        g_csrsrc[slot] = src;
        g_csrnorm[slot] = nv;
    }
}

__global__ void softmax4_kernel(const float* __restrict__ attn) {
    if (threadIdx.x == 0 && blockIdx.x == 0) {
        float m = attn[0];
        for (int p = 1; p < PP; p++) m = fmaxf(m, attn[p]);
        float s = 0.0f, e[PP];
        for (int p = 0; p < PP; p++) { e[p] = expf(attn[p] - m); s += e[p]; }
        for (int p = 0; p < PP; p++) g_probs[p] = e[p] / s;
    }
}

__global__ void wt_split_kernel(const float* __restrict__ W, int k0, int N, int Kb,
                                __nv_bfloat16* __restrict__ oh, __nv_bfloat16* __restrict__ ol) {
    int idx = blockIdx.x * blockDim.x + threadIdx.x;
    if (idx < N * Kb) {
        int n = idx / Kb;
        int k = idx - n * Kb;
        float v = W[(size_t)(k0 + k) * N + n];
        __nv_bfloat16 h, l;
        split_bf(v, h, l);
        oh[idx] = h; ol[idx] = l;
    }
}

__global__ void gatefold_kernel(const float* __restrict__ Wsm, const float* __restrict__ Lw,
                                float* __restrict__ M) {
    int idx = blockIdx.x * blockDim.x + threadIdx.x;
    if (idx < FF * CC) {
        int f = idx / CC, n = idx - f * CC;
        float s = 0.0f;
        for (int k = 0; k < CC; k++)
            s = fmaf(Wsm[(size_t)f * CC + k], Lw[(size_t)k * CC + n], s);
        M[idx] = s;
    }
}

__global__ void gate_bias_kernel(const float* __restrict__ Lw, const float* __restrict__ Lb,
                                 const float* __restrict__ bsmall, float* __restrict__ bv) {
    int n = blockIdx.x * blockDim.x + threadIdx.x;
    if (n < CC) {
        float s = Lb[n];
        for (int k = 0; k < CC; k++)
            s = fmaf(bsmall[k], Lw[(size_t)k * CC + n], s);
        bv[n] = s;
    }
}

// ---------------- bf16x3 tensor-core GEMM v3: BN=128, cp.async ----------------
#define BM 128
#define BN 128
#define BKC 32
#define TSTR 40
#define PL_SZ (128 * TSTR)           /* 5120 el per plane */
#define STG  (4 * PL_SZ)             /* Ah,Al,Bh,Bl */
#define SMEM_BYTES (2 * STG * 2)     /* 81920 B */

__device__ __forceinline__ void mma16816(float* c, const uint32_t* a, const uint32_t* b) {
    asm volatile(
        "mma.sync.aligned.m16n8k16.row.col.f32.bf16.bf16.f32 "
        "{%0,%1,%2,%3}, {%4,%5,%6,%7}, {%8,%9}, {%0,%1,%2,%3};"
        : "+f"(c[0]), "+f"(c[1]), "+f"(c[2]), "+f"(c[3])
        : "r"(a[0]), "r"(a[1]), "r"(a[2]), "r"(a[3]), "r"(b[0]), "r"(b[1]));
}

__device__ __forceinline__ void ldsm_x4(const void* p, uint32_t* r) {
    uint32_t addr = (uint32_t)__cvta_generic_to_shared(p);
    asm volatile("ldmatrix.sync.aligned.m8n8.x4.shared.b16 {%0,%1,%2,%3}, [%4];"
        : "=r"(r[0]), "=r"(r[1]), "=r"(r[2]), "=r"(r[3]) : "r"(addr));
}

__device__ __forceinline__ void cpa16(void* dst, const void* src, int sz) {
    uint32_t d = (uint32_t)__cvta_generic_to_shared(dst);
    asm volatile("cp.async.cg.shared.global [%0], [%1], 16, %2;"
                 :: "r"(d), "l"(src), "r"(sz));
}
__device__ __forceinline__ void cpa_commit() {
    asm volatile("cp.async.commit_group;");
}
template <int NW>
__device__ __forceinline__ void cpa_wait() {
    asm volatile("cp.async.wait_group %0;" :: "n"(NW));
}

// EPI: 0 store fp32; 1 split(acc+bias)->planes; 2 sigmoid(old+acc+bias)->fp32;
//      3 tanh(old+acc+bias)->fp32; 4 relu(acc+bias)->fp32;
//      5 sigmoid(old+acc+bias)*H->planes
template <int EPI>
__global__ void __launch_bounds__(256, 2) bf3_gemm(
    const __nv_bfloat16* __restrict__ Ah, const __nv_bfloat16* __restrict__ Al,
    const __nv_bfloat16* __restrict__ Bh, const __nv_bfloat16* __restrict__ Bl,
    float* __restrict__ Cm, const float* __restrict__ bias,
    const float* __restrict__ Hp,
    __nv_bfloat16* __restrict__ oh, __nv_bfloat16* __restrict__ ol,
    int M, int N, int K) {
    extern __shared__ __align__(16) __nv_bfloat16 sm[];

    int tid = threadIdx.x;
    int m0 = blockIdx.y * BM;
    int n0 = blockIdx.x * BN;
    int warp = tid >> 5, lane = tid & 31;
    int wm = warp >> 1, wn = warp & 1;   // 4M x 2N warps; warp tile 32x64
    int g = lane >> 2, tg = lane & 3;

    float c[2][8][4];
#pragma unroll
    for (int mt = 0; mt < 2; mt++)
#pragma unroll
        for (int nt = 0; nt < 8; nt++)
#pragma unroll
            for (int i = 0; i < 4; i++) c[mt][nt][i] = 0.0f;

    // each thread loads 2 chunks (16B) per plane per stage
    int r0 = tid >> 2, q0 = tid & 3;
    int r1 = (tid + 256) >> 2, q1 = (tid + 256) & 3;

    auto load_stage = [&](int st, int k0) {
        __nv_bfloat16* Ahs = sm + st * STG;
        __nv_bfloat16* Als = Ahs + PL_SZ;
        __nv_bfloat16* Bhs = Als + PL_SZ;
        __nv_bfloat16* Bls = Bhs + PL_SZ;
#pragma unroll
        for (int i = 0; i < 2; i++) {
            int row = i == 0 ? r0 : r1;
            int q = i == 0 ? q0 : q1;
            int m = m0 + row;
            int msz = (m < M) ? 16 : 0;
            size_t asrc = (size_t)(m < M ? m : 0) * K + k0 + q * 8;
            cpa16(Ahs + row * TSTR + q * 8, Ah + asrc, msz);
            cpa16(Als + row * TSTR + q * 8, Al + asrc, msz);
            size_t bsrc = (size_t)(n0 + row) * K + k0 + q * 8;
            cpa16(Bhs + row * TSTR + q * 8, Bh + bsrc, 16);
            cpa16(Bls + row * TSTR + q * 8, Bl + bsrc, 16);
        }
        cpa_commit();
    };

    auto compute = [&](int st) {
        const __nv_bfloat16* Ahs = sm + st * STG;
        const __nv_bfloat16* Als = Ahs + PL_SZ;
        const __nv_bfloat16* Bhs = Als + PL_SZ;
        const __nv_bfloat16* Bls = Bhs + PL_SZ;
#pragma unroll
        for (int ks = 0; ks < 2; ks++) {
            uint32_t ahf[2][4], alf[2][4];
            int arow = lane & 15;
            int acol = ks * 16 + (lane >> 4) * 8;
#pragma unroll
            for (int mt = 0; mt < 2; mt++) {
                int r = wm * 32 + mt * 16 + arow;
                ldsm_x4(Ahs + r * TSTR + acol, ahf[mt]);
                ldsm_x4(Als + r * TSTR + acol, alf[mt]);
            }
            uint32_t bf[8][2];
            int bm_ = lane >> 3;
            int brow_in = lane & 7;
            int bro = (bm_ >> 1) * 8 + brow_in;
            int bco = ks * 16 + (bm_ & 1) * 8;
            // B hi frags
#pragma unroll
            for (int ntp = 0; ntp < 4; ntp++) {
                int nr = wn * 64 + ntp * 16 + bro;
                uint32_t t4[4];
                ldsm_x4(Bhs + nr * TSTR + bco, t4);
                bf[ntp * 2][0] = t4[0]; bf[ntp * 2][1] = t4[1];
                bf[ntp * 2 + 1][0] = t4[2]; bf[ntp * 2 + 1][1] = t4[3];
            }
#pragma unroll
            for (int mt = 0; mt < 2; mt++)
#pragma unroll
                for (int nt = 0; nt < 8; nt++) {
                    mma16816(c[mt][nt], ahf[mt], bf[nt]);  // hi*hi
                    mma16816(c[mt][nt], alf[mt], bf[nt]);  // lo*hi
                }
            // B lo frags overwrite
#pragma unroll
            for (int ntp = 0; ntp < 4; ntp++) {
                int nr = wn * 64 + ntp * 16 + bro;
                uint32_t t4[4];
                ldsm_x4(Bls + nr * TSTR + bco, t4);
                bf[ntp * 2][0] = t4[0]; bf[ntp * 2][1] = t4[1];
                bf[ntp * 2 + 1][0] = t4[2]; bf[ntp * 2 + 1][1] = t4[3];
            }
#pragma unroll
            for (int mt = 0; mt < 2; mt++)
#pragma unroll
                for (int nt = 0; nt < 8; nt++)
                    mma16816(c[mt][nt], ahf[mt], bf[nt]);  // hi*lo
        }
    };

    int nchunks = K / BKC;
    load_stage(0, 0);
    for (int ch = 0; ch < nchunks; ch++) {
        int st = ch & 1;
        if (ch + 1 < nchunks) {
            load_stage(st ^ 1, (ch + 1) * BKC);
            cpa_wait<1>();
        } else {
            cpa_wait<0>();
        }
        __syncthreads();
        compute(st);
        __syncthreads();
    }

#pragma unroll
    for (int mt = 0; mt < 2; mt++) {
#pragma unroll
        for (int nt = 0; nt < 8; nt++) {
            int col = n0 + wn * 64 + nt * 8 + tg * 2;
            float bv0 = 0.f, bv1 = 0.f;
            if (EPI != 0) { bv0 = __ldg(&bias[col]); bv1 = __ldg(&bias[col + 1]); }
#pragma unroll
            for (int half = 0; half < 2; half++) {
                int row = m0 + wm * 32 + mt * 16 + g + half * 8;
                if (row >= M) continue;
                float v0 = c[mt][nt][half * 2 + 0];
                float v1 = c[mt][nt][half * 2 + 1];
                size_t off = (size_t)row * N + col;
                if (EPI == 0) {
                    *(float2*)(Cm + off) = make_float2(v0, v1);
                } else if (EPI == 1) {
                    float a0 = v0 + bv0, a1 = v1 + bv1;
                    *(uint32_t*)(oh + off) = split_pack(a0, a1);
                    *(uint32_t*)(ol + off) = split_pack_lo(a0, a1);
                } else if (EPI == 2) {
                    float2 old = *(float2*)(Cm + off);
                    float a0 = old.x + v0 + bv0, a1 = old.y + v1 + bv1;
                    *(float2*)(Cm + off) = make_float2(1.0f / (1.0f + expf(-a0)),
                                                       1.0f / (1.0f + expf(-a1)));
                } else if (EPI == 3) {
                    float2 old = *(float2*)(Cm + off);
                    *(float2*)(Cm + off) = make_float2(tanhf(old.x + v0 + bv0),
                                                       tanhf(old.y + v1 + bv1));
                } else if (EPI == 4) {
                    *(float2*)(Cm + off) = make_float2(fmaxf(v0 + bv0, 0.0f),
                                                       fmaxf(v1 + bv1, 0.0f));
                } else if (EPI == 5) {
                    float2 old = *(float2*)(Cm + off);
                    float sr0 = 1.0f / (1.0f + expf(-(old.x + v0 + bv0)));
                    float sr1 = 1.0f / (1.0f + expf(-(old.y + v1 + bv1)));
                    float2 hv = *(const float2*)(Hp + off);
                    float m0v = sr0 * hv.x, m1v = sr1 * hv.y;
                    *(uint32_t*)(oh + off) = split_pack(m0v, m1v);
                    *(uint32_t*)(ol + off) = split_pack_lo(m0v, m1v);
                }
            }
        }
    }
}

// ---------------- batched GCN propagation ----------------
template <bool WF32>
__global__ void __launch_bounds__(128) prop_split_kernel(
    const float* __restrict__ T, const float* __restrict__ bias,
    float* __restrict__ outf,
    __nv_bfloat16* __restrict__ oh, __nv_bfloat16* __restrict__ ol) {
    int r = blockIdx.x;
    int p = r / NN;
    int i = r - p * NN;
    int t = threadIdx.x;
    const float4* T4 = (const float4*)T;
    float4 b = ((const float4*)bias)[t];
    float sn = g_normself[i];
    float4 v = T4[(size_t)r * C4 + t];
    float4 acc = make_float4(b.x + sn * v.x, b.y + sn * v.y, b.z + sn * v.z, b.w + sn * v.w);
    int beg = g_rowptr[i];
    int end = g_rowptr[i + 1];
    int base = p * NN;
    for (int e = beg; e < end; e++) {
        int s = g_csrsrc[e];
        float w = g_csrnorm[e];
        float4 u = T4[(size_t)(base + s) * C4 + t];
        acc.x = fmaf(w, u.x, acc.x);
        acc.y = fmaf(w, u.y, acc.y);
        acc.z = fmaf(w, u.z, acc.z);
        acc.w = fmaf(w, u.w, acc.w);
    }
    if (WF32) ((float4*)outf)[(size_t)r * C4 + t] = acc;
    size_t off = (size_t)r * CC + t * 4;
    *(uint32_t*)(oh + off) = split_pack(acc.x, acc.y);
    *(uint32_t*)(oh + off + 2) = split_pack(acc.z, acc.w);
    *(uint32_t*)(ol + off) = split_pack_lo(acc.x, acc.y);
    *(uint32_t*)(ol + off + 2) = split_pack_lo(acc.z, acc.w);
}

__global__ void __launch_bounds__(128) prop128_kernel(
    const float* __restrict__ Xp,
    __nv_bfloat16* __restrict__ oh, __nv_bfloat16* __restrict__ ol) {
    int r = blockIdx.x * 4 + (threadIdx.x >> 5);
    int t = threadIdx.x & 31;
    if (r >= MB) return;
    int p = r / NN;
    int i = r - p * NN;
    const float4* X4 = (const float4*)Xp;
    float sn = g_normself[i];
    float4 v = X4[(size_t)r * F4 + t];
    float4 acc = make_float4(sn * v.x, sn * v.y, sn * v.z, sn * v.w);
    int beg = g_rowptr[i];
    int end = g_rowptr[i + 1];
    int base = p * NN;
    for (int e = beg; e < end; e++) {
        int s = g_csrsrc[e];
        float w = g_csrnorm[e];
        float4 u = X4[(size_t)(base + s) * F4 + t];
        acc.x = fmaf(w, u.x, acc.x);
        acc.y = fmaf(w, u.y, acc.y);
        acc.z = fmaf(w, u.z, acc.z);
        acc.w = fmaf(w, u.w, acc.w);
    }
    size_t off = (size_t)r * FF + t * 4;
    *(uint32_t*)(oh + off) = split_pack(acc.x, acc.y);
    *(uint32_t*)(oh + off + 2) = split_pack(acc.z, acc.w);
    *(uint32_t*)(ol + off) = split_pack_lo(acc.x, acc.y);
    *(uint32_t*)(ol + off + 2) = split_pack_lo(acc.z, acc.w);
}

// ---------------- elementwise kernels ----------------
__global__ void extract_all_kernel(const float* __restrict__ x, float* __restrict__ Xp) {
    int idx = blockIdx.x * blockDim.x + threadIdx.x;
    if (idx < NN * FF) {
        float4 v = ((const float4*)x)[idx];
        Xp[idx] = v.x;
        Xp[NN * FF + idx] = v.y;
        Xp[2 * NN * FF + idx] = v.z;
        Xp[3 * NN * FF + idx] = v.w;
    }
}

__global__ void gru_reduce_kernel(const float* __restrict__ Z, const float* __restrict__ H,
                                  const float* __restrict__ Ht, float* __restrict__ out,
                                  __nv_bfloat16* __restrict__ oh, __nv_bfloat16* __restrict__ ol) {
    int idx = blockIdx.x * blockDim.x + threadIdx.x;
    if (idx >= NN * C4) return;
    int i = idx >> 7;
    int t = idx & 127;
    float4 acc = make_float4(0.f, 0.f, 0.f, 0.f);
#pragma unroll
    for (int p = 0; p < PP; p++) {
        size_t o4 = (size_t)(p * NN + i) * C4 + t;
        float4 z = ((const float4*)Z)[o4];
        float4 h = ((const float4*)H)[o4];
        float4 ht = ((const float4*)Ht)[o4];
        float pr = g_probs[p];
        acc.x += pr * (z.x * h.x + (1.0f - z.x) * ht.x);
        acc.y += pr * (z.y * h.y + (1.0f - z.y) * ht.y);
        acc.z += pr * (z.z * h.z + (1.0f - z.z) * ht.z);
        acc.w += pr * (z.w * h.w + (1.0f - z.w) * ht.w);
    }
    ((float4*)(out + NN))[idx] = acc;
    float4 v = make_float4(fmaxf(acc.x, 0.f), fmaxf(acc.y, 0.f),
                           fmaxf(acc.z, 0.f), fmaxf(acc.w, 0.f));
    size_t off = (size_t)idx * 4;
    *(uint32_t*)(oh + off) = split_pack(v.x, v.y);
    *(uint32_t*)(oh + off + 2) = split_pack(v.z, v.w);
    *(uint32_t*)(ol + off) = split_pack_lo(v.x, v.y);
    *(uint32_t*)(ol + off + 2) = split_pack_lo(v.z, v.w);
}

__global__ void lin2_kernel(const float* __restrict__ hid, const float* __restrict__ w,
                            const float* __restrict__ b, float* __restrict__ out) {
    int n = blockIdx.x * 8 + (threadIdx.x >> 5);
    int lane = threadIdx.x & 31;
    float s = 0.0f;
    for (int k = lane; k < HIDN; k += 32) s = fmaf(hid[(size_t)n * HIDN + k], w[k], s);
#pragma unroll
    for (int off = 16; off; off >>= 1) s += __shfl_down_sync(0xffffffffu, s, off);
    if (lane == 0) out[n] = s + b[0];
}

// ---------------- host orchestration ----------------
#define GP(sym) ({ void* _p; cudaGetSymbolAddress(&_p, sym); (__nv_bfloat16*)_p; })
#define GPF(sym) ({ void* _p; cudaGetSymbolAddress(&_p, sym); (float*)_p; })

struct GemmArgs {
    const __nv_bfloat16 *Ah, *Al, *Bh, *Bl;
    float* Cm;
    const float* bias;
    const float* Hp;
    __nv_bfloat16 *oh, *ol;
    int M, N, K;
};

template <int EPI>
static inline void launch_gemm(const GemmArgs& a) {
    dim3 grid(a.N / BN, (a.M + BM - 1) / BM);
    bf3_gemm<EPI><<<grid, 256, SMEM_BYTES>>>(a.Ah, a.Al, a.Bh, a.Bl, a.Cm, a.bias,
                                             a.Hp, a.oh, a.ol, a.M, a.N, a.K);
}

extern "C" void kernel_launch(void* const* d_in, const int* in_sizes, int n_in,
                              void* d_out, int out_size) {
    const float* x     = (const float*)d_in[0];
    const int*   ei    = (const int*)d_in[1];
    const float* ea    = (const float*)d_in[2];
    const float* W1    = (const float*)d_in[3];
    const float* b1    = (const float*)d_in[4];
    const float* W2    = (const float*)d_in[5];
    const float* b2    = (const float*)d_in[6];
    const float* W3    = (const float*)d_in[7];
    const float* b3    = (const float*)d_in[8];
    const float* W4    = (const float*)d_in[9];
    const float* b4    = (const float*)d_in[10];
    const float* W5    = (const float*)d_in[11];
    const float* b5    = (const float*)d_in[12];
    const float* Wz    = (const float*)d_in[13];
    const float* bz    = (const float*)d_in[14];
    const float* Lz_w  = (const float*)d_in[15];
    const float* Lz_b  = (const float*)d_in[16];
    const float* Wr    = (const float*)d_in[17];
    const float* br    = (const float*)d_in[18];
    const float* Lr_w  = (const float*)d_in[19];
    const float* Lr_b  = (const float*)d_in[20];
    const float* Wh    = (const float*)d_in[21];
    const float* bh    = (const float*)d_in[22];
    const float* Lh_w  = (const float*)d_in[23];
    const float* Lh_b  = (const float*)d_in[24];
    const float* attn  = (const float*)d_in[25];
    const float* lin1w = (const float*)d_in[26];
    const float* lin1b = (const float*)d_in[27];
    const float* lin2w = (const float*)d_in[28];
    const float* lin2b = (const float*)d_in[29];
    float* out = (float*)d_out;

    static bool attr_done = false;
    if (!attr_done) {
        cudaFuncSetAttribute(bf3_gemm<0>, cudaFuncAttributeMaxDynamicSharedMemorySize, SMEM_BYTES);
        cudaFuncSetAttribute(bf3_gemm<1>, cudaFuncAttributeMaxDynamicSharedMemorySize, SMEM_BYTES);
        cudaFuncSetAttribute(bf3_gemm<2>, cudaFuncAttributeMaxDynamicSharedMemorySize, SMEM_BYTES);
        cudaFuncSetAttribute(bf3_gemm<3>, cudaFuncAttributeMaxDynamicSharedMemorySize, SMEM_BYTES);
        cudaFuncSetAttribute(bf3_gemm<4>, cudaFuncAttributeMaxDynamicSharedMemorySize, SMEM_BYTES);
        cudaFuncSetAttribute(bf3_gemm<5>, cudaFuncAttributeMaxDynamicSharedMemorySize, SMEM_BYTES);
        attr_done = true;
    }

    float* pXp   = GPF(g_Xp);
    float* pT    = GPF(g_T);
    float* pH    = GPF(g_H);
    float* pZ    = GPF(g_Z);
    float* pHt   = GPF(g_Ht);
    float* phid1 = GPF(g_hid1);
    float* pMtmp = GPF(g_Mtmp);
    float* pbvz  = GPF(g_bvz);
    float* pbvr  = GPF(g_bvr);
    float* pbvh  = GPF(g_bvh);

    __nv_bfloat16 *pXsh = GP(g_Xsh), *pXsl = GP(g_Xsl);
    __nv_bfloat16 *pBAh = GP(g_BAh), *pBAl = GP(g_BAl);
    __nv_bfloat16 *pBBh = GP(g_BBh), *pBBl = GP(g_BBl);
    __nv_bfloat16 *pHh = GP(g_Hh), *pHl = GP(g_Hl);
    __nv_bfloat16 *pRmh = GP(g_Rmh), *pRml = GP(g_Rml);
    __nv_bfloat16 *pRAh = GP(g_RAh), *pRAl = GP(g_RAl);

    __nv_bfloat16 *pW1h = GP(g_W1h), *pW1l = GP(g_W1l);
    __nv_bfloat16 *pW2h = GP(g_W2h), *pW2l = GP(g_W2l);
    __nv_bfloat16 *pW3h = GP(g_W3h), *pW3l = GP(g_W3l);
    __nv_bfloat16 *pW4h = GP(g_W4h), *pW4l = GP(g_W4l);
    __nv_bfloat16 *pW5h = GP(g_W5h), *pW5l = GP(g_W5l);
    __nv_bfloat16 *pMzh = GP(g_Mzh), *pMzl = GP(g_Mzl);
    __nv_bfloat16 *pMrh = GP(g_Mrh), *pMrl = GP(g_Mrl);
    __nv_bfloat16 *pMhh = GP(g_Mhh), *pMhl = GP(g_Mhl);
    __nv_bfloat16 *pLz2h = GP(g_Lz2h), *pLz2l = GP(g_Lz2l);
    __nv_bfloat16 *pLr2h = GP(g_Lr2h), *pLr2l = GP(g_Lr2l);
    __nv_bfloat16 *pLh2h = GP(g_Lh2h), *pLh2l = GP(g_Lh2l);
    __nv_bfloat16 *pL1th = GP(g_L1th), *pL1tl = GP(g_L1tl);

    const int gE  = (EE + 255) / 256;
    const int gN  = (NN + 255) / 256;
    const int gNC4 = (NN * C4 + 255) / 256;
    const int gNF = (NN * FF + 255) / 256;
    const int gW512 = (CC * CC + 255) / 256;
    const int gW128 = (CC * FF + 255) / 256;
    const int gWL1 = (HIDN * CC + 255) / 256;

    init_node_arrays<<<gN, 256>>>();
    deg_edges_kernel<<<gE, 256>>>(ei, ea);
    deg_finalize_kernel<<<gN, 256>>>();
    scan_kernel<<<1, 1024>>>();
    scatter_kernel<<<gE, 256>>>(ei, ea);
    softmax4_kernel<<<1, 32>>>(attn);

    wt_split_kernel<<<gW128, 256>>>(W1, 0, CC, FF, pW1h, pW1l);
    wt_split_kernel<<<gW512, 256>>>(W2, 0, CC, CC, pW2h, pW2l);
    wt_split_kernel<<<gW512, 256>>>(W3, 0, CC, CC, pW3h, pW3l);
    wt_split_kernel<<<gW512, 256>>>(W4, 0, CC, CC, pW4h, pW4l);
    wt_split_kernel<<<gW512, 256>>>(W5, 0, CC, CC, pW5h, pW5l);
    wt_split_kernel<<<gW512, 256>>>(Lz_w, CC, CC, CC, pLz2h, pLz2l);
    wt_split_kernel<<<gW512, 256>>>(Lr_w, CC, CC, CC, pLr2h, pLr2l);
    wt_split_kernel<<<gW512, 256>>>(Lh_w, CC, CC, CC, pLh2h, pLh2l);
    wt_split_kernel<<<gWL1, 256>>>(lin1w, 0, HIDN, CC, pL1th, pL1tl);

    gatefold_kernel<<<gW128, 256>>>(Wz, Lz_w, pMtmp);
    wt_split_kernel<<<gW128, 256>>>(pMtmp, 0, CC, FF, pMzh, pMzl);
    gatefold_kernel<<<gW128, 256>>>(Wr, Lr_w, pMtmp);
    wt_split_kernel<<<gW128, 256>>>(pMtmp, 0, CC, FF, pMrh, pMrl);
    gatefold_kernel<<<gW128, 256>>>(Wh, Lh_w, pMtmp);
    wt_split_kernel<<<gW128, 256>>>(pMtmp, 0, CC, FF, pMhh, pMhl);
    gate_bias_kernel<<<2, 256>>>(Lz_w, Lz_b, bz, pbvz);
    gate_bias_kernel<<<2, 256>>>(Lr_w, Lr_b, br, pbvr);
    gate_bias_kernel<<<2, 256>>>(Lh_w, Lh_b, bh, pbvh);

    // ---- batched across all 4 timesteps (M = 40000) ----
    extract_all_kernel<<<gNF, 256>>>(x, pXp);
    prop128_kernel<<<(MB + 3) / 4, 128>>>(pXp, pXsh, pXsl);

    GemmArgs a{};
    a = {pXsh, pXsl, pW1h, pW1l, nullptr, b1, nullptr, pBAh, pBAl, MB, CC, FF};
    launch_gemm<1>(a);
    a = {pBAh, pBAl, pW2h, pW2l, pT, nullptr, nullptr, nullptr, nullptr, MB, CC, CC};
    launch_gemm<0>(a);
    prop_split_kernel<false><<<MB, 128>>>(pT, b2, nullptr, pBBh, pBBl);
    a.Ah = pBBh; a.Al = pBBl; a.Bh = pW3h; a.Bl = pW3l;
    launch_gemm<0>(a);
    prop_split_kernel<false><<<MB, 128>>>(pT, b3, nullptr, pBAh, pBAl);
    a.Ah = pBAh; a.Al = pBAl; a.Bh = pW4h; a.Bl = pW4l;
    launch_gemm<0>(a);
    prop_split_kernel<false><<<MB, 128>>>(pT, b4, nullptr, pBBh, pBBl);
    a.Ah = pBBh; a.Al = pBBl; a.Bh = pW5h; a.Bl = pW5l;
    launch_gemm<0>(a);
    prop_split_kernel<true><<<MB, 128>>>(pT, b5, pH, pHh, pHl);

    a = {pXsh, pXsl, pMzh, pMzl, pZ, nullptr, nullptr, nullptr, nullptr, MB, CC, FF};
    launch_gemm<0>(a);
    a = {pHh, pHl, pLz2h, pLz2l, pZ, pbvz, nullptr, nullptr, nullptr, MB, CC, CC};
    launch_gemm<2>(a);

    a = {pXsh, pXsl, pMrh, pMrl, pT, nullptr, nullptr, nullptr, nullptr, MB, CC, FF};
    launch_gemm<0>(a);
    a = {pHh, pHl, pLr2h, pLr2l, pT, pbvr, pH, pRmh, pRml, MB, CC, CC};
    launch_gemm<5>(a);

    a = {pXsh, pXsl, pMhh, pMhl, pHt, nullptr, nullptr, nullptr, nullptr, MB, CC, FF};
    launch_gemm<0>(a);
    a = {pRmh, pRml, pLh2h, pLh2l, pHt, pbvh, nullptr, nullptr, nullptr, MB, CC, CC};
    launch_gemm<3>(a);

    gru_reduce_kernel<<<gNC4, 256>>>(pZ, pH, pHt, out, pRAh, pRAl);

    a = {pRAh, pRAl, pL1th, pL1tl, phid1, lin1b, nullptr, nullptr, nullptr, NN, HIDN, CC};
    launch_gemm<4>(a);
    lin2_kernel<<<(NN + 7) / 8, 256>>>(phid1, lin2w, lin2b, out);
}